// round 4
// baseline (speedup 1.0000x reference)
#include <cuda_runtime.h>
#include <cuda_fp16.h>
#include <cstdint>

// ---------------- problem constants ----------------
#define NMAX   50048      // padded node capacity
#define EMAX   800000
#define GMAX   64
#define HD     128        // hidden dim (H*D)
#define PW     512        // q|k|v|skip packed row width

// ---------------- static scratch (no allocs allowed) ----------------
__device__ float   g_P[(size_t)NMAX * PW];    // packed projections q|k|v|s (fp32)
__device__ __half2 g_KV[(size_t)NMAX * 128];  // per node: k (64 half2) | v (64 half2)
__device__ float   g_H0[(size_t)NMAX * HD];   // layer0 output (post relu)
__device__ float   g_H1[(size_t)NMAX * HD];   // layer1 output (post relu)
__device__ int     g_deg[NMAX];
__device__ int     g_cnt[NMAX];
__device__ int     g_rowptr[NMAX + 1];
__device__ int     g_src[EMAX];
__device__ float   g_attr[EMAX];
__device__ int     g_ghist[GMAX];
__device__ int     g_gstart[GMAX + 1];
__device__ float   g_pool[GMAX * HD];

// ---------------- CSR build ----------------
__global__ void zero_kernel(int N) {
    int i = blockIdx.x * blockDim.x + threadIdx.x;
    if (i < N) { g_deg[i] = 0; g_cnt[i] = 0; }
    if (i < GMAX) g_ghist[i] = 0;
}

__global__ void hist_kernel(const int* __restrict__ dst,
                            const int* __restrict__ batch, int N, int E) {
    int i = blockIdx.x * blockDim.x + threadIdx.x;
    if (i < E) atomicAdd(&g_deg[dst[i]], 1);
    if (i < N) atomicAdd(&g_ghist[batch[i]], 1);
}

__global__ void scan_kernel(int N) {
    __shared__ int sums[1024];
    int t = threadIdx.x;
    int chunk = (N + 1023) >> 10;
    int lo = t * chunk;
    int hi = min(lo + chunk, N);
    int s = 0;
    for (int i = lo; i < hi; i++) s += g_deg[i];
    sums[t] = s;
    __syncthreads();
    for (int off = 1; off < 1024; off <<= 1) {
        int v = (t >= off) ? sums[t - off] : 0;
        __syncthreads();
        sums[t] += v;
        __syncthreads();
    }
    int run = sums[t] - s;   // exclusive prefix
    for (int i = lo; i < hi; i++) { g_rowptr[i] = run; run += g_deg[i]; }
    if (t == 1023) g_rowptr[N] = sums[1023];
    if (t == 0) {
        int r = 0;
        for (int g = 0; g < GMAX; g++) { g_gstart[g] = r; r += g_ghist[g]; }
        g_gstart[GMAX] = r;
    }
}

__global__ void scatter_kernel(const int* __restrict__ src,
                               const int* __restrict__ dst,
                               const float* __restrict__ attr, int E) {
    int i = blockIdx.x * blockDim.x + threadIdx.x;
    if (i >= E) return;
    int d = dst[i];
    int p = g_rowptr[d] + atomicAdd(&g_cnt[d], 1);
    g_src[p]  = src[i];
    g_attr[p] = attr[i];
}

// ---------------- layer-0 projections (in_ch = 2), fused fp16 k/v copies ----------------
__global__ void proj0_kernel(const float* __restrict__ x,
                             const float* __restrict__ Wq, const float* __restrict__ bq,
                             const float* __restrict__ Wk, const float* __restrict__ bk,
                             const float* __restrict__ Wv, const float* __restrict__ bv,
                             const float* __restrict__ Ws, const float* __restrict__ bs,
                             int N) {
    int idx = blockIdx.x * blockDim.x + threadIdx.x;     // one float4 of P
    if (idx >= N * 128) return;
    int n  = idx >> 7;
    int c4 = idx & 127;            // float4 index within 512-wide row
    int sel = c4 >> 5;             // 0=q 1=k 2=v 3=skip
    int sc4 = c4 & 31;             // float4 index within 128-wide section
    int cc  = sc4 * 4;
    const float* W; const float* b;
    if (sel == 0)      { W = Wq; b = bq; }
    else if (sel == 1) { W = Wk; b = bk; }
    else if (sel == 2) { W = Wv; b = bv; }
    else               { W = Ws; b = bs; }
    float x0 = x[2 * n], x1 = x[2 * n + 1];
    float4 w0 = *(const float4*)(W + cc);
    float4 w1 = *(const float4*)(W + 128 + cc);
    float4 bb = *(const float4*)(b + cc);
    float4 r;
    r.x = fmaf(x0, w0.x, fmaf(x1, w1.x, bb.x));
    r.y = fmaf(x0, w0.y, fmaf(x1, w1.y, bb.y));
    r.z = fmaf(x0, w0.z, fmaf(x1, w1.z, bb.z));
    r.w = fmaf(x0, w0.w, fmaf(x1, w1.w, bb.w));
    ((float4*)g_P)[(size_t)n * 128 + c4] = r;
    if (sel == 1 || sel == 2) {
        size_t kvi = (size_t)n * 128 + (sel == 2 ? 64 : 0) + sc4 * 2;
        g_KV[kvi]     = __floats2half2_rn(r.x, r.y);
        g_KV[kvi + 1] = __floats2half2_rn(r.z, r.w);
    }
}

// ---------------- layer-1 projections: 3xTF32 tensor-core GEMM ----------------
#define SA 20     // A smem panel stride (16 + 4 pad)
#define SB 136    // B smem panel stride (128 + 8 pad)

__device__ __forceinline__ void split_tf32(float x, uint32_t& hi, uint32_t& lo) {
    uint32_t h;
    asm("cvt.rna.tf32.f32 %0, %1;" : "=r"(h) : "f"(x));
    float r = x - __uint_as_float(h);
    uint32_t l;
    asm("cvt.rna.tf32.f32 %0, %1;" : "=r"(l) : "f"(r));
    hi = h; lo = l;
}

__device__ __forceinline__ void mma8(float* c, const uint32_t* a, const uint32_t* b) {
    asm volatile(
        "mma.sync.aligned.m16n8k8.row.col.f32.tf32.tf32.f32 "
        "{%0,%1,%2,%3}, {%4,%5,%6,%7}, {%8,%9}, {%0,%1,%2,%3};"
        : "+f"(c[0]), "+f"(c[1]), "+f"(c[2]), "+f"(c[3])
        : "r"(a[0]), "r"(a[1]), "r"(a[2]), "r"(a[3]), "r"(b[0]), "r"(b[1]));
}

__global__ __launch_bounds__(256, 2) void gemm3_kernel(
    const float* __restrict__ Wq, const float* __restrict__ Wk,
    const float* __restrict__ Wv, const float* __restrict__ Ws,
    const float* __restrict__ bq, const float* __restrict__ bk,
    const float* __restrict__ bv, const float* __restrict__ bs) {
    __shared__ uint32_t AsH[128][SA];
    __shared__ uint32_t AsL[128][SA];
    __shared__ uint32_t BsH[16][SB];
    __shared__ uint32_t BsL[16][SB];

    const float* W; const float* bias;
    int sec = blockIdx.y;
    if (sec == 0)      { W = Wq; bias = bq; }
    else if (sec == 1) { W = Wk; bias = bk; }
    else if (sec == 2) { W = Wv; bias = bv; }
    else               { W = Ws; bias = bs; }

    int tid  = threadIdx.x;
    int warp = tid >> 5, lane = tid & 31;
    int g    = lane >> 2, tig = lane & 3;
    int wm   = warp >> 2, wn = warp & 3;         // 2 x 4 warp grid
    int blockM = blockIdx.x * 128;

    float acc[4][4][4];
#pragma unroll
    for (int mt = 0; mt < 4; mt++)
#pragma unroll
        for (int nt = 0; nt < 4; nt++)
#pragma unroll
            for (int c = 0; c < 4; c++) acc[mt][nt][c] = 0.f;

#pragma unroll 1
    for (int kp = 0; kp < 8; kp++) {
        int k0 = kp * 16;
        __syncthreads();
#pragma unroll
        for (int j = 0; j < 2; j++) {
            int pos = tid + 256 * j;
            int row = pos >> 2;
            int c4  = pos & 3;
            float4 v = *(const float4*)(g_H0 + (size_t)(blockM + row) * 128 + k0 + c4 * 4);
            uint4 h, l;
            split_tf32(v.x, h.x, l.x);
            split_tf32(v.y, h.y, l.y);
            split_tf32(v.z, h.z, l.z);
            split_tf32(v.w, h.w, l.w);
            *(uint4*)&AsH[row][c4 * 4] = h;
            *(uint4*)&AsL[row][c4 * 4] = l;
        }
#pragma unroll
        for (int j = 0; j < 2; j++) {
            int pos = tid + 256 * j;
            int row = pos >> 5;
            int c4  = pos & 31;
            float4 v = *(const float4*)(W + (size_t)(k0 + row) * 128 + c4 * 4);
            uint4 h, l;
            split_tf32(v.x, h.x, l.x);
            split_tf32(v.y, h.y, l.y);
            split_tf32(v.z, h.z, l.z);
            split_tf32(v.w, h.w, l.w);
            *(uint4*)&BsH[row][c4 * 4] = h;
            *(uint4*)&BsL[row][c4 * 4] = l;
        }
        __syncthreads();

#pragma unroll
        for (int ks = 0; ks < 2; ks++) {
            int kk = ks * 8;
            uint32_t bh[4][2], bl[4][2];
#pragma unroll
            for (int nt = 0; nt < 4; nt++) {
                int col = wn * 32 + nt * 8 + g;
                bh[nt][0] = BsH[kk + tig][col];
                bh[nt][1] = BsH[kk + tig + 4][col];
                bl[nt][0] = BsL[kk + tig][col];
                bl[nt][1] = BsL[kk + tig + 4][col];
            }
#pragma unroll
            for (int mt = 0; mt < 4; mt++) {
                int r0 = wm * 64 + mt * 16 + g;
                uint32_t ah[4], al[4];
                ah[0] = AsH[r0][kk + tig];
                ah[1] = AsH[r0 + 8][kk + tig];
                ah[2] = AsH[r0][kk + tig + 4];
                ah[3] = AsH[r0 + 8][kk + tig + 4];
                al[0] = AsL[r0][kk + tig];
                al[1] = AsL[r0 + 8][kk + tig];
                al[2] = AsL[r0][kk + tig + 4];
                al[3] = AsL[r0 + 8][kk + tig + 4];
#pragma unroll
                for (int nt = 0; nt < 4; nt++) {
                    mma8(acc[mt][nt], ah, bh[nt]);   // hi*hi
                    mma8(acc[mt][nt], ah, bl[nt]);   // hi*lo
                    mma8(acc[mt][nt], al, bh[nt]);   // lo*hi
                }
            }
        }
    }

    int secOff = sec * 128;
    bool isKV = (sec == 1 || sec == 2);
    int kvOff = (sec == 2) ? 64 : 0;
#pragma unroll
    for (int mt = 0; mt < 4; mt++) {
        int r0 = blockM + wm * 64 + mt * 16 + g;
#pragma unroll
        for (int nt = 0; nt < 4; nt++) {
            int cn = wn * 32 + nt * 8 + tig * 2;
            float b0 = bias[cn], b1 = bias[cn + 1];
            float2 v0 = make_float2(acc[mt][nt][0] + b0, acc[mt][nt][1] + b1);
            float2 v1 = make_float2(acc[mt][nt][2] + b0, acc[mt][nt][3] + b1);
            *(float2*)(g_P + (size_t)r0 * PW + secOff + cn)       = v0;
            *(float2*)(g_P + (size_t)(r0 + 8) * PW + secOff + cn) = v1;
            if (isKV) {
                g_KV[(size_t)r0 * 128 + kvOff + cn / 2]       = __floats2half2_rn(v0.x, v0.y);
                g_KV[(size_t)(r0 + 8) * 128 + kvOff + cn / 2] = __floats2half2_rn(v1.x, v1.y);
            }
        }
    }
}

// ---------------- edge attention: warp/node, dual-state online softmax ----------------
// fp16 gathers of k,v (512 B/edge); q/skip fp32 from g_P.
__device__ __forceinline__ float4 ldg_kv4(const __half2* p) {
    uint2 r = __ldg((const uint2*)p);
    __half2 h0 = *reinterpret_cast<__half2*>(&r.x);
    __half2 h1 = *reinterpret_cast<__half2*>(&r.y);
    float2 a = __half22float2(h0);
    float2 b = __half22float2(h1);
    return make_float4(a.x, a.y, b.x, b.y);
}

__device__ __forceinline__ float dot_reduce16(float4 q, float4 k) {
    float part = q.x * k.x + q.y * k.y + q.z * k.z + q.w * k.w;
    part += __shfl_xor_sync(0xffffffffu, part, 8, 16);
    part += __shfl_xor_sync(0xffffffffu, part, 4, 16);
    part += __shfl_xor_sync(0xffffffffu, part, 2, 16);
    part += __shfl_xor_sync(0xffffffffu, part, 1, 16);
    return part * 0.125f;   // / sqrt(64)
}

__global__ void attn_kernel(const float* __restrict__ We, int which, int N) {
    int gt   = blockIdx.x * blockDim.x + threadIdx.x;
    int lane = threadIdx.x & 31;
    int n    = gt >> 5;
    if (n >= N) return;

    const float4* P4 = (const float4*)g_P;
    size_t base = (size_t)n * 128;
    float4 qv = __ldg(P4 + base + lane);
    float4 we = __ldg(((const float4*)We) + lane);

    float4 accA = make_float4(0.f, 0.f, 0.f, 0.f);
    float4 accB = make_float4(0.f, 0.f, 0.f, 0.f);
    float mA = -1e30f, mB = -1e30f;
    float dA = 0.f,    dB = 0.f;

    int beg = g_rowptr[n], end = g_rowptr[n + 1];
    int i = beg;
    for (; i + 1 < end; i += 2) {
        int   s0 = __ldg(g_src + i);
        int   s1 = __ldg(g_src + i + 1);
        float a0 = __ldg(g_attr + i);
        float a1 = __ldg(g_attr + i + 1);
        const __half2* kv0 = g_KV + (size_t)s0 * 128 + lane * 2;
        const __half2* kv1 = g_KV + (size_t)s1 * 128 + lane * 2;

        float4 k0 = ldg_kv4(kv0);
        float4 k1 = ldg_kv4(kv1);
        float4 v0 = ldg_kv4(kv0 + 64);
        float4 v1 = ldg_kv4(kv1 + 64);

        k0.x = fmaf(a0, we.x, k0.x); k0.y = fmaf(a0, we.y, k0.y);
        k0.z = fmaf(a0, we.z, k0.z); k0.w = fmaf(a0, we.w, k0.w);
        k1.x = fmaf(a1, we.x, k1.x); k1.y = fmaf(a1, we.y, k1.y);
        k1.z = fmaf(a1, we.z, k1.z); k1.w = fmaf(a1, we.w, k1.w);

        float l0 = dot_reduce16(qv, k0);
        float l1 = dot_reduce16(qv, k1);

        v0.x = fmaf(a0, we.x, v0.x); v0.y = fmaf(a0, we.y, v0.y);
        v0.z = fmaf(a0, we.z, v0.z); v0.w = fmaf(a0, we.w, v0.w);
        v1.x = fmaf(a1, we.x, v1.x); v1.y = fmaf(a1, we.y, v1.y);
        v1.z = fmaf(a1, we.z, v1.z); v1.w = fmaf(a1, we.w, v1.w);

        {
            float nm = fmaxf(mA, l0);
            float sc = __expf(mA - nm);
            float ex = __expf(l0 - nm);
            accA.x = fmaf(accA.x, sc, ex * v0.x);
            accA.y = fmaf(accA.y, sc, ex * v0.y);
            accA.z = fmaf(accA.z, sc, ex * v0.z);
            accA.w = fmaf(accA.w, sc, ex * v0.w);
            dA = fmaf(dA, sc, ex);
            mA = nm;
        }
        {
            float nm = fmaxf(mB, l1);
            float sc = __expf(mB - nm);
            float ex = __expf(l1 - nm);
            accB.x = fmaf(accB.x, sc, ex * v1.x);
            accB.y = fmaf(accB.y, sc, ex * v1.y);
            accB.z = fmaf(accB.z, sc, ex * v1.z);
            accB.w = fmaf(accB.w, sc, ex * v1.w);
            dB = fmaf(dB, sc, ex);
            mB = nm;
        }
    }
    if (i < end) {   // odd tail -> state A
        int   s0 = __ldg(g_src + i);
        float a0 = __ldg(g_attr + i);
        const __half2* kv0 = g_KV + (size_t)s0 * 128 + lane * 2;
        float4 k0 = ldg_kv4(kv0);
        float4 v0 = ldg_kv4(kv0 + 64);
        k0.x = fmaf(a0, we.x, k0.x); k0.y = fmaf(a0, we.y, k0.y);
        k0.z = fmaf(a0, we.z, k0.z); k0.w = fmaf(a0, we.w, k0.w);
        float l0 = dot_reduce16(qv, k0);
        v0.x = fmaf(a0, we.x, v0.x); v0.y = fmaf(a0, we.y, v0.y);
        v0.z = fmaf(a0, we.z, v0.z); v0.w = fmaf(a0, we.w, v0.w);
        float nm = fmaxf(mA, l0);
        float sc = __expf(mA - nm);
        float ex = __expf(l0 - nm);
        accA.x = fmaf(accA.x, sc, ex * v0.x);
        accA.y = fmaf(accA.y, sc, ex * v0.y);
        accA.z = fmaf(accA.z, sc, ex * v0.z);
        accA.w = fmaf(accA.w, sc, ex * v0.w);
        dA = fmaf(dA, sc, ex);
        mA = nm;
    }

    // exact merge of the two states
    float nm = fmaxf(mA, mB);
    float eA = __expf(mA - nm);
    float eB = __expf(mB - nm);
    float den = dA * eA + dB * eB;
    float4 acc;
    acc.x = accA.x * eA + accB.x * eB;
    acc.y = accA.y * eA + accB.y * eB;
    acc.z = accA.z * eA + accB.z * eB;
    acc.w = accA.w * eA + accB.w * eB;

    float inv = 1.f / (den + 1e-16f);
    float4 sk = __ldg(P4 + base + 96 + lane);
    float4 o;
    o.x = fmaxf(fmaf(acc.x, inv, sk.x), 0.f);
    o.y = fmaxf(fmaf(acc.y, inv, sk.y), 0.f);
    o.z = fmaxf(fmaf(acc.z, inv, sk.z), 0.f);
    o.w = fmaxf(fmaf(acc.w, inv, sk.w), 0.f);
    float* H = which ? g_H1 : g_H0;
    ((float4*)H)[(size_t)n * 32 + lane] = o;
}

// ---------------- graph mean pool (batch is sorted) ----------------
__global__ void pool_kernel() {
    int g = blockIdx.x;
    int t = threadIdx.x;
    int b0 = g_gstart[g], b1 = g_gstart[g + 1];
    float acc = 0.f;
#pragma unroll 4
    for (int n = b0; n < b1; n++) acc += g_H1[(size_t)n * HD + t];
    float c = (float)max(b1 - b0, 1);
    g_pool[g * HD + t] = acc / c;
}

// ---------------- classifier head ----------------
__global__ void classifier_kernel(const float* __restrict__ cW1, const float* __restrict__ cb1,
                                  const float* __restrict__ cW2, const float* __restrict__ cb2,
                                  float* __restrict__ out) {
    __shared__ float gs[HD];
    __shared__ float hid[HD];
    int g = blockIdx.x;
    int t = threadIdx.x;
    gs[t] = g_pool[g * HD + t];
    __syncthreads();
    float acc = cb1[t];
#pragma unroll 8
    for (int c = 0; c < HD; c++) acc = fmaf(gs[c], cW1[c * 128 + t], acc);
    hid[t] = fmaxf(acc, 0.f);
    __syncthreads();
    if (t < 30) {
        float o = cb2[t];
#pragma unroll 8
        for (int j = 0; j < HD; j++) o = fmaf(hid[j], cW2[j * 30 + t], o);
        out[g * 30 + t] = o;
    }
}

// ---------------- launch ----------------
extern "C" void kernel_launch(void* const* d_in, const int* in_sizes, int n_in,
                              void* d_out, int out_size) {
    const float* x      = (const float*)d_in[0];
    const int*   ei     = (const int*)d_in[1];
    const float* eattr  = (const float*)d_in[2];
    const int*   batch  = (const int*)d_in[3];
    const float* l0_Wq = (const float*)d_in[4];
    const float* l0_bq = (const float*)d_in[5];
    const float* l0_Wk = (const float*)d_in[6];
    const float* l0_bk = (const float*)d_in[7];
    const float* l0_Wv = (const float*)d_in[8];
    const float* l0_bv = (const float*)d_in[9];
    const float* l0_We = (const float*)d_in[10];
    const float* l0_Ws = (const float*)d_in[11];
    const float* l0_bs = (const float*)d_in[12];
    const float* l1_Wq = (const float*)d_in[13];
    const float* l1_bq = (const float*)d_in[14];
    const float* l1_Wk = (const float*)d_in[15];
    const float* l1_bk = (const float*)d_in[16];
    const float* l1_Wv = (const float*)d_in[17];
    const float* l1_bv = (const float*)d_in[18];
    const float* l1_We = (const float*)d_in[19];
    const float* l1_Ws = (const float*)d_in[20];
    const float* l1_bs = (const float*)d_in[21];
    const float* cW1   = (const float*)d_in[22];
    const float* cb1   = (const float*)d_in[23];
    const float* cW2   = (const float*)d_in[24];
    const float* cb2   = (const float*)d_in[25];
    float* out = (float*)d_out;

    int N = in_sizes[3];       // batch length = #nodes
    int E = in_sizes[2];       // edge_attr length = #edges
    const int* src = ei;
    const int* dst = ei + E;

    // CSR build (reused by both layers)
    zero_kernel<<<(N + 255) / 256, 256>>>(N);
    hist_kernel<<<(E + 255) / 256, 256>>>(dst, batch, N, E);
    scan_kernel<<<1, 1024>>>(N);
    scatter_kernel<<<(E + 255) / 256, 256>>>(src, dst, eattr, E);

    // layer 0
    proj0_kernel<<<(N * 128 + 255) / 256, 256>>>(x, l0_Wq, l0_bq, l0_Wk, l0_bk,
                                                 l0_Wv, l0_bv, l0_Ws, l0_bs, N);
    attn_kernel<<<(N * 32 + 255) / 256, 256>>>(l0_We, 0, N);

    // layer 1 projections: fused 3xTF32 tensor-core GEMM, all 4 weights
    dim3 ggrid((N + 127) / 128, 4);
    gemm3_kernel<<<ggrid, 256>>>(l1_Wq, l1_Wk, l1_Wv, l1_Ws,
                                 l1_bq, l1_bk, l1_bv, l1_bs);

    attn_kernel<<<(N * 32 + 255) / 256, 256>>>(l1_We, 1, N);

    // pool + head
    pool_kernel<<<GMAX, HD>>>();
    classifier_kernel<<<GMAX, HD>>>(cW1, cb1, cW2, cb2, out);
}

// round 5
// speedup vs baseline: 1.2053x; 1.2053x over previous
#include <cuda_runtime.h>
#include <cuda_fp16.h>
#include <cstdint>

// ---------------- problem constants ----------------
#define NMAX   50048      // padded node capacity
#define EMAX   800000
#define GMAX   64
#define HD     128        // hidden dim (H*D)
#define PW     256        // q|skip packed row width (k/v live in g_KV fp16)

// ---------------- static scratch (no allocs allowed) ----------------
__device__ float   g_P[(size_t)NMAX * PW];    // packed q|s (fp32)
__device__ __half2 g_KV[(size_t)NMAX * 128];  // per node: k (64 half2) | v (64 half2)
__device__ float   g_H0[(size_t)NMAX * HD];   // layer0 output (post relu)
__device__ float   g_H1[(size_t)NMAX * HD];   // layer1 output (post relu)
__device__ int     g_deg[NMAX];
__device__ int     g_cnt[NMAX];
__device__ int     g_rowptr[NMAX + 1];
__device__ int     g_src[EMAX];
__device__ float   g_attr[EMAX];
__device__ int     g_ghist[GMAX];
__device__ int     g_gstart[GMAX + 1];
__device__ float   g_poolp[GMAX * 8 * HD];    // partial pool sums

// ---------------- CSR build ----------------
__global__ void zero_kernel(int N) {
    int i = blockIdx.x * blockDim.x + threadIdx.x;
    if (i < N) { g_deg[i] = 0; g_cnt[i] = 0; }
    if (i < GMAX) g_ghist[i] = 0;
}

__global__ void hist_kernel(const int* __restrict__ dst,
                            const int* __restrict__ batch, int N, int E) {
    int i = blockIdx.x * blockDim.x + threadIdx.x;
    if (i < E) atomicAdd(&g_deg[dst[i]], 1);
    if (i < N) atomicAdd(&g_ghist[batch[i]], 1);
}

__global__ void scan_kernel(int N) {
    __shared__ int sums[1024];
    int t = threadIdx.x;
    int chunk = (N + 1023) >> 10;
    int lo = t * chunk;
    int hi = min(lo + chunk, N);
    int s = 0;
    for (int i = lo; i < hi; i++) s += g_deg[i];
    sums[t] = s;
    __syncthreads();
    for (int off = 1; off < 1024; off <<= 1) {
        int v = (t >= off) ? sums[t - off] : 0;
        __syncthreads();
        sums[t] += v;
        __syncthreads();
    }
    int run = sums[t] - s;   // exclusive prefix
    for (int i = lo; i < hi; i++) { g_rowptr[i] = run; run += g_deg[i]; }
    if (t == 1023) g_rowptr[N] = sums[1023];
    if (t == 0) {
        int r = 0;
        for (int g = 0; g < GMAX; g++) { g_gstart[g] = r; r += g_ghist[g]; }
        g_gstart[GMAX] = r;
    }
}

__global__ void scatter_kernel(const int* __restrict__ src,
                               const int* __restrict__ dst,
                               const float* __restrict__ attr, int E) {
    int i = blockIdx.x * blockDim.x + threadIdx.x;
    if (i >= E) return;
    int d = dst[i];
    int p = g_rowptr[d] + atomicAdd(&g_cnt[d], 1);
    g_src[p]  = src[i];
    g_attr[p] = attr[i];
}

// ---------------- layer-0 projections (in_ch = 2) ----------------
// q,s -> fp32 g_P (row = 64 float4: q 0..31 | s 32..63); k,v -> fp16 g_KV only.
__global__ void proj0_kernel(const float* __restrict__ x,
                             const float* __restrict__ Wq, const float* __restrict__ bq,
                             const float* __restrict__ Wk, const float* __restrict__ bk,
                             const float* __restrict__ Wv, const float* __restrict__ bv,
                             const float* __restrict__ Ws, const float* __restrict__ bs,
                             int N) {
    int idx = blockIdx.x * blockDim.x + threadIdx.x;
    if (idx >= N * 128) return;
    int n  = idx >> 7;
    int c4 = idx & 127;            // which float4 of the 4x128 outputs
    int sel = c4 >> 5;             // 0=q 1=k 2=v 3=skip
    int sc4 = c4 & 31;
    int cc  = sc4 * 4;
    const float* W; const float* b;
    if (sel == 0)      { W = Wq; b = bq; }
    else if (sel == 1) { W = Wk; b = bk; }
    else if (sel == 2) { W = Wv; b = bv; }
    else               { W = Ws; b = bs; }
    float x0 = x[2 * n], x1 = x[2 * n + 1];
    float4 w0 = *(const float4*)(W + cc);
    float4 w1 = *(const float4*)(W + 128 + cc);
    float4 bb = *(const float4*)(b + cc);
    float4 r;
    r.x = fmaf(x0, w0.x, fmaf(x1, w1.x, bb.x));
    r.y = fmaf(x0, w0.y, fmaf(x1, w1.y, bb.y));
    r.z = fmaf(x0, w0.z, fmaf(x1, w1.z, bb.z));
    r.w = fmaf(x0, w0.w, fmaf(x1, w1.w, bb.w));
    if (sel == 0) {
        ((float4*)g_P)[(size_t)n * 64 + sc4] = r;
    } else if (sel == 3) {
        ((float4*)g_P)[(size_t)n * 64 + 32 + sc4] = r;
    } else {
        size_t kvi = (size_t)n * 128 + (sel == 2 ? 64 : 0) + sc4 * 2;
        g_KV[kvi]     = __floats2half2_rn(r.x, r.y);
        g_KV[kvi + 1] = __floats2half2_rn(r.z, r.w);
    }
}

// ---------------- layer-1 projections: 3xTF32 tensor-core GEMM ----------------
#define SA 20     // A smem panel stride (16 + 4 pad)
#define SB 136    // B smem panel stride (128 + 8 pad)

__device__ __forceinline__ void split_tf32(float x, uint32_t& hi, uint32_t& lo) {
    uint32_t h;
    asm("cvt.rna.tf32.f32 %0, %1;" : "=r"(h) : "f"(x));
    float r = x - __uint_as_float(h);
    uint32_t l;
    asm("cvt.rna.tf32.f32 %0, %1;" : "=r"(l) : "f"(r));
    hi = h; lo = l;
}

__device__ __forceinline__ void mma8(float* c, const uint32_t* a, const uint32_t* b) {
    asm volatile(
        "mma.sync.aligned.m16n8k8.row.col.f32.tf32.tf32.f32 "
        "{%0,%1,%2,%3}, {%4,%5,%6,%7}, {%8,%9}, {%0,%1,%2,%3};"
        : "+f"(c[0]), "+f"(c[1]), "+f"(c[2]), "+f"(c[3])
        : "r"(a[0]), "r"(a[1]), "r"(a[2]), "r"(a[3]), "r"(b[0]), "r"(b[1]));
}

__global__ __launch_bounds__(256, 2) void gemm3_kernel(
    const float* __restrict__ Wq, const float* __restrict__ Wk,
    const float* __restrict__ Wv, const float* __restrict__ Ws,
    const float* __restrict__ bq, const float* __restrict__ bk,
    const float* __restrict__ bv, const float* __restrict__ bs) {
    __shared__ uint32_t AsH[128][SA];
    __shared__ uint32_t AsL[128][SA];
    __shared__ uint32_t BsH[16][SB];
    __shared__ uint32_t BsL[16][SB];

    const float* W; const float* bias;
    int sec = blockIdx.y;
    if (sec == 0)      { W = Wq; bias = bq; }
    else if (sec == 1) { W = Wk; bias = bk; }
    else if (sec == 2) { W = Wv; bias = bv; }
    else               { W = Ws; bias = bs; }

    int tid  = threadIdx.x;
    int warp = tid >> 5, lane = tid & 31;
    int g    = lane >> 2, tig = lane & 3;
    int wm   = warp >> 2, wn = warp & 3;         // 2 x 4 warp grid
    int blockM = blockIdx.x * 128;

    float acc[4][4][4];
#pragma unroll
    for (int mt = 0; mt < 4; mt++)
#pragma unroll
        for (int nt = 0; nt < 4; nt++)
#pragma unroll
            for (int c = 0; c < 4; c++) acc[mt][nt][c] = 0.f;

#pragma unroll 1
    for (int kp = 0; kp < 8; kp++) {
        int k0 = kp * 16;
        __syncthreads();
#pragma unroll
        for (int j = 0; j < 2; j++) {
            int pos = tid + 256 * j;
            int row = pos >> 2;
            int c4  = pos & 3;
            float4 v = *(const float4*)(g_H0 + (size_t)(blockM + row) * 128 + k0 + c4 * 4);
            uint4 h, l;
            split_tf32(v.x, h.x, l.x);
            split_tf32(v.y, h.y, l.y);
            split_tf32(v.z, h.z, l.z);
            split_tf32(v.w, h.w, l.w);
            *(uint4*)&AsH[row][c4 * 4] = h;
            *(uint4*)&AsL[row][c4 * 4] = l;
        }
#pragma unroll
        for (int j = 0; j < 2; j++) {
            int pos = tid + 256 * j;
            int row = pos >> 5;
            int c4  = pos & 31;
            float4 v = *(const float4*)(W + (size_t)(k0 + row) * 128 + c4 * 4);
            uint4 h, l;
            split_tf32(v.x, h.x, l.x);
            split_tf32(v.y, h.y, l.y);
            split_tf32(v.z, h.z, l.z);
            split_tf32(v.w, h.w, l.w);
            *(uint4*)&BsH[row][c4 * 4] = h;
            *(uint4*)&BsL[row][c4 * 4] = l;
        }
        __syncthreads();

#pragma unroll
        for (int ks = 0; ks < 2; ks++) {
            int kk = ks * 8;
            uint32_t bh[4][2], bl[4][2];
#pragma unroll
            for (int nt = 0; nt < 4; nt++) {
                int col = wn * 32 + nt * 8 + g;
                bh[nt][0] = BsH[kk + tig][col];
                bh[nt][1] = BsH[kk + tig + 4][col];
                bl[nt][0] = BsL[kk + tig][col];
                bl[nt][1] = BsL[kk + tig + 4][col];
            }
#pragma unroll
            for (int mt = 0; mt < 4; mt++) {
                int r0 = wm * 64 + mt * 16 + g;
                uint32_t ah[4], al[4];
                ah[0] = AsH[r0][kk + tig];
                ah[1] = AsH[r0 + 8][kk + tig];
                ah[2] = AsH[r0][kk + tig + 4];
                ah[3] = AsH[r0 + 8][kk + tig + 4];
                al[0] = AsL[r0][kk + tig];
                al[1] = AsL[r0 + 8][kk + tig];
                al[2] = AsL[r0][kk + tig + 4];
                al[3] = AsL[r0 + 8][kk + tig + 4];
#pragma unroll
                for (int nt = 0; nt < 4; nt++) {
                    mma8(acc[mt][nt], ah, bh[nt]);   // hi*hi
                    mma8(acc[mt][nt], ah, bl[nt]);   // hi*lo
                    mma8(acc[mt][nt], al, bh[nt]);   // lo*hi
                }
            }
        }
    }

    // epilogue: q -> P cols 0..127; s -> P cols 128..255; k/v -> fp16 KV only
    bool isKV = (sec == 1 || sec == 2);
    int kvOff = (sec == 2) ? 64 : 0;
    int pOff  = (sec == 3) ? 128 : 0;
#pragma unroll
    for (int mt = 0; mt < 4; mt++) {
        int r0 = blockM + wm * 64 + mt * 16 + g;
#pragma unroll
        for (int nt = 0; nt < 4; nt++) {
            int cn = wn * 32 + nt * 8 + tig * 2;
            float b0 = bias[cn], b1 = bias[cn + 1];
            float2 v0 = make_float2(acc[mt][nt][0] + b0, acc[mt][nt][1] + b1);
            float2 v1 = make_float2(acc[mt][nt][2] + b0, acc[mt][nt][3] + b1);
            if (isKV) {
                g_KV[(size_t)r0 * 128 + kvOff + cn / 2]       = __floats2half2_rn(v0.x, v0.y);
                g_KV[(size_t)(r0 + 8) * 128 + kvOff + cn / 2] = __floats2half2_rn(v1.x, v1.y);
            } else {
                *(float2*)(g_P + (size_t)r0 * PW + pOff + cn)       = v0;
                *(float2*)(g_P + (size_t)(r0 + 8) * PW + pOff + cn) = v1;
            }
        }
    }
}

// ---------------- edge attention: warp/node, dual-state online softmax ----------------
// logit = (q.k_src + a*(q.We))/8 ; agg = (Sum ex*v_src + (Sum ex*a)*We)/den
__device__ __forceinline__ float4 ldg_kv4(const __half2* p) {
    uint2 r = __ldg((const uint2*)p);
    __half2 h0 = *reinterpret_cast<__half2*>(&r.x);
    __half2 h1 = *reinterpret_cast<__half2*>(&r.y);
    float2 a = __half22float2(h0);
    float2 b = __half22float2(h1);
    return make_float4(a.x, a.y, b.x, b.y);
}

__device__ __forceinline__ float dot_reduce16(float4 q, float4 k) {
    float part = q.x * k.x + q.y * k.y + q.z * k.z + q.w * k.w;
    part += __shfl_xor_sync(0xffffffffu, part, 8, 16);
    part += __shfl_xor_sync(0xffffffffu, part, 4, 16);
    part += __shfl_xor_sync(0xffffffffu, part, 2, 16);
    part += __shfl_xor_sync(0xffffffffu, part, 1, 16);
    return part;
}

__global__ void attn_kernel(const float* __restrict__ We, int which, int N) {
    int gt   = blockIdx.x * blockDim.x + threadIdx.x;
    int lane = threadIdx.x & 31;
    int n    = gt >> 5;
    if (n >= N) return;

    const float4* P4 = (const float4*)g_P;
    size_t base = (size_t)n * 64;
    float4 qv = __ldg(P4 + base + lane);
    float4 we = __ldg(((const float4*)We) + lane);
    float qWe = dot_reduce16(qv, we);    // per-head scalar (uniform in 16-lane half)

    float4 accA = make_float4(0.f, 0.f, 0.f, 0.f);
    float4 accB = make_float4(0.f, 0.f, 0.f, 0.f);
    float mA = -1e30f, mB = -1e30f;
    float dA = 0.f,    dB = 0.f;
    float sA = 0.f,    sB = 0.f;         // Sum ex * attr

    int beg = g_rowptr[n], end = g_rowptr[n + 1];
    int i = beg;
    for (; i + 1 < end; i += 2) {
        int   s0 = __ldg(g_src + i);
        int   s1 = __ldg(g_src + i + 1);
        float a0 = __ldg(g_attr + i);
        float a1 = __ldg(g_attr + i + 1);
        const __half2* kv0 = g_KV + (size_t)s0 * 128 + lane * 2;
        const __half2* kv1 = g_KV + (size_t)s1 * 128 + lane * 2;

        float4 k0 = ldg_kv4(kv0);
        float4 k1 = ldg_kv4(kv1);
        float4 v0 = ldg_kv4(kv0 + 64);
        float4 v1 = ldg_kv4(kv1 + 64);

        float l0 = (dot_reduce16(qv, k0) + a0 * qWe) * 0.125f;
        float l1 = (dot_reduce16(qv, k1) + a1 * qWe) * 0.125f;

        {
            float nm = fmaxf(mA, l0);
            float sc = __expf(mA - nm);
            float ex = __expf(l0 - nm);
            accA.x = fmaf(accA.x, sc, ex * v0.x);
            accA.y = fmaf(accA.y, sc, ex * v0.y);
            accA.z = fmaf(accA.z, sc, ex * v0.z);
            accA.w = fmaf(accA.w, sc, ex * v0.w);
            dA = fmaf(dA, sc, ex);
            sA = fmaf(sA, sc, ex * a0);
            mA = nm;
        }
        {
            float nm = fmaxf(mB, l1);
            float sc = __expf(mB - nm);
            float ex = __expf(l1 - nm);
            accB.x = fmaf(accB.x, sc, ex * v1.x);
            accB.y = fmaf(accB.y, sc, ex * v1.y);
            accB.z = fmaf(accB.z, sc, ex * v1.z);
            accB.w = fmaf(accB.w, sc, ex * v1.w);
            dB = fmaf(dB, sc, ex);
            sB = fmaf(sB, sc, ex * a1);
            mB = nm;
        }
    }
    if (i < end) {   // odd tail -> state A
        int   s0 = __ldg(g_src + i);
        float a0 = __ldg(g_attr + i);
        const __half2* kv0 = g_KV + (size_t)s0 * 128 + lane * 2;
        float4 k0 = ldg_kv4(kv0);
        float4 v0 = ldg_kv4(kv0 + 64);
        float l0 = (dot_reduce16(qv, k0) + a0 * qWe) * 0.125f;
        float nm = fmaxf(mA, l0);
        float sc = __expf(mA - nm);
        float ex = __expf(l0 - nm);
        accA.x = fmaf(accA.x, sc, ex * v0.x);
        accA.y = fmaf(accA.y, sc, ex * v0.y);
        accA.z = fmaf(accA.z, sc, ex * v0.z);
        accA.w = fmaf(accA.w, sc, ex * v0.w);
        dA = fmaf(dA, sc, ex);
        sA = fmaf(sA, sc, ex * a0);
        mA = nm;
    }

    // exact merge of the two states
    float nm = fmaxf(mA, mB);
    float eA = __expf(mA - nm);
    float eB = __expf(mB - nm);
    float den  = dA * eA + dB * eB;
    float sSum = sA * eA + sB * eB;
    float4 acc;
    acc.x = fmaf(accA.x, eA, accB.x * eB);
    acc.y = fmaf(accA.y, eA, accB.y * eB);
    acc.z = fmaf(accA.z, eA, accB.z * eB);
    acc.w = fmaf(accA.w, eA, accB.w * eB);
    // add back the We contribution: + sSum * We
    acc.x = fmaf(sSum, we.x, acc.x);
    acc.y = fmaf(sSum, we.y, acc.y);
    acc.z = fmaf(sSum, we.z, acc.z);
    acc.w = fmaf(sSum, we.w, acc.w);

    float inv = 1.f / (den + 1e-16f);
    float4 sk = __ldg(P4 + base + 32 + lane);
    float4 o;
    o.x = fmaxf(fmaf(acc.x, inv, sk.x), 0.f);
    o.y = fmaxf(fmaf(acc.y, inv, sk.y), 0.f);
    o.z = fmaxf(fmaf(acc.z, inv, sk.z), 0.f);
    o.w = fmaxf(fmaf(acc.w, inv, sk.w), 0.f);
    float* H = which ? g_H1 : g_H0;
    ((float4*)H)[(size_t)n * 32 + lane] = o;
}

// ---------------- graph mean pool, two-stage (batch is sorted) ----------------
__global__ void pool_kernel() {
    int g = blockIdx.x;
    int c = blockIdx.y;          // 0..7 partial
    int t = threadIdx.x;
    int b0 = g_gstart[g], b1 = g_gstart[g + 1];
    int len = b1 - b0;
    int chunk = (len + 7) >> 3;
    int lo = b0 + c * chunk;
    int hi = min(lo + chunk, b1);
    float acc = 0.f;
#pragma unroll 4
    for (int n = lo; n < hi; n++) acc += g_H1[(size_t)n * HD + t];
    g_poolp[((size_t)g * 8 + c) * HD + t] = acc;
}

// ---------------- classifier head (folds pool reduction) ----------------
__global__ void classifier_kernel(const float* __restrict__ cW1, const float* __restrict__ cb1,
                                  const float* __restrict__ cW2, const float* __restrict__ cb2,
                                  float* __restrict__ out) {
    __shared__ float gs[HD];
    __shared__ float hid[HD];
    int g = blockIdx.x;
    int t = threadIdx.x;
    float s = 0.f;
#pragma unroll
    for (int c = 0; c < 8; c++) s += g_poolp[((size_t)g * 8 + c) * HD + t];
    float cnt = (float)max(g_gstart[g + 1] - g_gstart[g], 1);
    gs[t] = s / cnt;
    __syncthreads();
    float acc = cb1[t];
#pragma unroll 8
    for (int c = 0; c < HD; c++) acc = fmaf(gs[c], cW1[c * 128 + t], acc);
    hid[t] = fmaxf(acc, 0.f);
    __syncthreads();
    if (t < 30) {
        float o = cb2[t];
#pragma unroll 8
        for (int j = 0; j < HD; j++) o = fmaf(hid[j], cW2[j * 30 + t], o);
        out[g * 30 + t] = o;
    }
}

// ---------------- launch ----------------
extern "C" void kernel_launch(void* const* d_in, const int* in_sizes, int n_in,
                              void* d_out, int out_size) {
    const float* x      = (const float*)d_in[0];
    const int*   ei     = (const int*)d_in[1];
    const float* eattr  = (const float*)d_in[2];
    const int*   batch  = (const int*)d_in[3];
    const float* l0_Wq = (const float*)d_in[4];
    const float* l0_bq = (const float*)d_in[5];
    const float* l0_Wk = (const float*)d_in[6];
    const float* l0_bk = (const float*)d_in[7];
    const float* l0_Wv = (const float*)d_in[8];
    const float* l0_bv = (const float*)d_in[9];
    const float* l0_We = (const float*)d_in[10];
    const float* l0_Ws = (const float*)d_in[11];
    const float* l0_bs = (const float*)d_in[12];
    const float* l1_Wq = (const float*)d_in[13];
    const float* l1_bq = (const float*)d_in[14];
    const float* l1_Wk = (const float*)d_in[15];
    const float* l1_bk = (const float*)d_in[16];
    const float* l1_Wv = (const float*)d_in[17];
    const float* l1_bv = (const float*)d_in[18];
    const float* l1_We = (const float*)d_in[19];
    const float* l1_Ws = (const float*)d_in[20];
    const float* l1_bs = (const float*)d_in[21];
    const float* cW1   = (const float*)d_in[22];
    const float* cb1   = (const float*)d_in[23];
    const float* cW2   = (const float*)d_in[24];
    const float* cb2   = (const float*)d_in[25];
    float* out = (float*)d_out;

    int N = in_sizes[3];       // batch length = #nodes
    int E = in_sizes[2];       // edge_attr length = #edges
    const int* src = ei;
    const int* dst = ei + E;

    // CSR build (reused by both layers)
    zero_kernel<<<(N + 255) / 256, 256>>>(N);
    hist_kernel<<<(E + 255) / 256, 256>>>(dst, batch, N, E);
    scan_kernel<<<1, 1024>>>(N);
    scatter_kernel<<<(E + 255) / 256, 256>>>(src, dst, eattr, E);

    // layer 0
    proj0_kernel<<<(N * 128 + 255) / 256, 256>>>(x, l0_Wq, l0_bq, l0_Wk, l0_bk,
                                                 l0_Wv, l0_bv, l0_Ws, l0_bs, N);
    attn_kernel<<<(N * 32 + 255) / 256, 256>>>(l0_We, 0, N);

    // layer 1 projections: fused 3xTF32 tensor-core GEMM, all 4 weights
    dim3 ggrid((N + 127) / 128, 4);
    gemm3_kernel<<<ggrid, 256>>>(l1_Wq, l1_Wk, l1_Wv, l1_Ws,
                                 l1_bq, l1_bk, l1_bv, l1_bs);

    attn_kernel<<<(N * 32 + 255) / 256, 256>>>(l1_We, 1, N);

    // pool (two-stage) + head
    dim3 pgrid(GMAX, 8);
    pool_kernel<<<pgrid, HD>>>();
    classifier_kernel<<<GMAX, HD>>>(cW1, cb1, cW2, cb2, out);
}

// round 6
// speedup vs baseline: 1.3933x; 1.1560x over previous
#include <cuda_runtime.h>
#include <cuda_fp16.h>
#include <cstdint>

// ---------------- problem constants ----------------
#define NMAX   50048      // padded node capacity
#define EMAX   800000
#define GMAX   64
#define HD     128        // hidden dim (H*D)
#define PW     256        // q|skip packed row width for layer 1

// ---------------- static scratch (no allocs allowed) ----------------
__device__ float   g_P[(size_t)NMAX * PW];    // layer1 packed q|s (fp32)
__device__ __half2 g_KV[(size_t)NMAX * 128];  // layer1 per node: k | v (fp16)
__device__ float   g_H0[(size_t)NMAX * HD];   // layer0 output (post relu)
__device__ float   g_H1[(size_t)NMAX * HD];   // layer1 output (post relu)
__device__ float   g_A[(size_t)NMAX * 8];     // layer0 compact attn results (2 heads x float4)
__device__ float   g_M0[18];                  // layer0 3x3 bilinear forms (2 heads)
__device__ float   g_cq0[6];                  // layer0 q.We coefficient 3-vectors (2 heads)
__device__ int     g_deg[NMAX];
__device__ int     g_cnt[NMAX];
__device__ int     g_rowptr[NMAX + 1];
__device__ int     g_src[EMAX];
__device__ float   g_attr[EMAX];
__device__ int     g_ghist[GMAX];
__device__ int     g_gstart[GMAX + 1];
__device__ float   g_poolp[GMAX * 8 * HD];    // partial pool sums

// ---------------- CSR build ----------------
__global__ void zero_kernel(int N) {
    int i = blockIdx.x * blockDim.x + threadIdx.x;
    if (i < N) { g_deg[i] = 0; g_cnt[i] = 0; }
    if (i < GMAX) g_ghist[i] = 0;
}

__global__ void hist_kernel(const int* __restrict__ dst,
                            const int* __restrict__ batch, int N, int E) {
    int i = blockIdx.x * blockDim.x + threadIdx.x;
    if (i < E) atomicAdd(&g_deg[dst[i]], 1);
    if (i < N) atomicAdd(&g_ghist[batch[i]], 1);
}

__global__ void scan_kernel(int N) {
    __shared__ int sums[1024];
    int t = threadIdx.x;
    int chunk = (N + 1023) >> 10;
    int lo = t * chunk;
    int hi = min(lo + chunk, N);
    int s = 0;
    for (int i = lo; i < hi; i++) s += g_deg[i];
    sums[t] = s;
    __syncthreads();
    for (int off = 1; off < 1024; off <<= 1) {
        int v = (t >= off) ? sums[t - off] : 0;
        __syncthreads();
        sums[t] += v;
        __syncthreads();
    }
    int run = sums[t] - s;   // exclusive prefix
    for (int i = lo; i < hi; i++) { g_rowptr[i] = run; run += g_deg[i]; }
    if (t == 1023) g_rowptr[N] = sums[1023];
    if (t == 0) {
        int r = 0;
        for (int g = 0; g < GMAX; g++) { g_gstart[g] = r; r += g_ghist[g]; }
        g_gstart[GMAX] = r;
    }
}

__global__ void scatter_kernel(const int* __restrict__ src,
                               const int* __restrict__ dst,
                               const float* __restrict__ attr, int E) {
    int i = blockIdx.x * blockDim.x + threadIdx.x;
    if (i >= E) return;
    int d = dst[i];
    int p = g_rowptr[d] + atomicAdd(&g_cnt[d], 1);
    g_src[p]  = src[i];
    g_attr[p] = attr[i];
}

// ---------------- layer-0 precompute: 3x3 bilinear forms ----------------
// M_h[r][c] = dot(rowQ_r, rowK_c) over head slice (rowQ_0=Wq[0,:], rowQ_1=Wq[1,:], rowQ_2=bq)
// cq_h[r]   = dot(rowQ_r, We) over head slice
__global__ void prep0_kernel(const float* __restrict__ Wq, const float* __restrict__ bq,
                             const float* __restrict__ Wk, const float* __restrict__ bk,
                             const float* __restrict__ We) {
    int t = threadIdx.x;
    if (t < 18) {
        int h = t / 9, rem = t % 9, r = rem / 3, c = rem % 3;
        const float* qrow = (r < 2) ? (Wq + r * 128 + h * 64) : (bq + h * 64);
        const float* krow = (c < 2) ? (Wk + c * 128 + h * 64) : (bk + h * 64);
        float s = 0.f;
#pragma unroll 8
        for (int d = 0; d < 64; d++) s += qrow[d] * krow[d];
        g_M0[t] = s;
    } else if (t < 24) {
        int j = t - 18;
        int h = j / 3, r = j % 3;
        const float* qrow = (r < 2) ? (Wq + r * 128 + h * 64) : (bq + h * 64);
        const float* we = We + h * 64;
        float s = 0.f;
#pragma unroll 8
        for (int d = 0; d < 64; d++) s += qrow[d] * we[d];
        g_cq0[j] = s;
    }
}

// ---------------- layer-0 attention: one THREAD per node, scalar states ----------------
__global__ void attn0_kernel(const float* __restrict__ x, int N) {
    __shared__ float sM[18], sC[6];
    int t = threadIdx.x;
    if (t < 18) sM[t] = g_M0[t];
    if (t < 6)  sC[t] = g_cq0[t];
    __syncthreads();

    int n = blockIdx.x * blockDim.x + t;
    if (n >= N) return;

    const float2* x2 = (const float2*)x;
    float2 xd = __ldg(x2 + n);

    float w[2][3], cqd[2];
#pragma unroll
    for (int h = 0; h < 2; h++) {
#pragma unroll
        for (int j = 0; j < 3; j++)
            w[h][j] = fmaf(xd.x, sM[h * 9 + j], fmaf(xd.y, sM[h * 9 + 3 + j], sM[h * 9 + 6 + j]));
        cqd[h] = fmaf(xd.x, sC[h * 3], fmaf(xd.y, sC[h * 3 + 1], sC[h * 3 + 2]));
    }

    float m[2]   = {-1e30f, -1e30f};
    float den[2] = {0.f, 0.f};
    float S0[2]  = {0.f, 0.f};
    float S1[2]  = {0.f, 0.f};
    float Sa[2]  = {0.f, 0.f};

    int beg = g_rowptr[n], end = g_rowptr[n + 1];
    // software pipeline: prefetch next edge
    int sNxt = 0; float aNxt = 0.f; float2 xsNxt = make_float2(0.f, 0.f);
    if (beg < end) {
        sNxt = __ldg(g_src + beg);
        aNxt = __ldg(g_attr + beg);
        xsNxt = __ldg(x2 + sNxt);
    }
    for (int i = beg; i < end; i++) {
        float a = aNxt; float2 xs = xsNxt;
        if (i + 1 < end) {
            sNxt = __ldg(g_src + i + 1);
            aNxt = __ldg(g_attr + i + 1);
            xsNxt = __ldg(x2 + sNxt);
        }
#pragma unroll
        for (int h = 0; h < 2; h++) {
            float l = fmaf(a, cqd[h],
                      fmaf(xs.x, w[h][0], fmaf(xs.y, w[h][1], w[h][2]))) * 0.125f;
            float nm = fmaxf(m[h], l);
            float sc = __expf(m[h] - nm);
            float ex = __expf(l - nm);
            S0[h] = fmaf(S0[h], sc, ex * xs.x);
            S1[h] = fmaf(S1[h], sc, ex * xs.y);
            Sa[h] = fmaf(Sa[h], sc, ex * a);
            den[h] = fmaf(den[h], sc, ex);
            m[h] = nm;
        }
    }

    float4* A4 = (float4*)g_A;
#pragma unroll
    for (int h = 0; h < 2; h++) {
        float inv = 1.f / (den[h] + 1e-16f);
        A4[(size_t)n * 2 + h] = make_float4(S0[h] * inv, S1[h] * inv, Sa[h] * inv, 0.f);
    }
}

// ---------------- layer-0 expansion: H0 = relu(A0*Wv0 + A1*Wv1 + bv + Aa*We + x@Ws + bs) ----------------
__global__ void expand0_kernel(const float* __restrict__ x,
                               const float* __restrict__ Wv, const float* __restrict__ bv,
                               const float* __restrict__ We,
                               const float* __restrict__ Ws, const float* __restrict__ bs,
                               int N) {
    int idx = blockIdx.x * blockDim.x + threadIdx.x;
    if (idx >= N * 32) return;
    int n  = idx >> 5;
    int c4 = idx & 31;          // float4 column index (0..31 covers 128)
    int h  = c4 >> 4;
    int cc = c4 * 4;

    float4 wv0 = *(const float4*)(Wv + cc);
    float4 wv1 = *(const float4*)(Wv + 128 + cc);
    float4 bbv = *(const float4*)(bv + cc);
    float4 wee = *(const float4*)(We + cc);
    float4 ws0 = *(const float4*)(Ws + cc);
    float4 ws1 = *(const float4*)(Ws + 128 + cc);
    float4 bbs = *(const float4*)(bs + cc);

    float2 xn = __ldg((const float2*)x + n);
    float4 A  = __ldg(((const float4*)g_A) + (size_t)n * 2 + h);

    float4 r;
    r.x = fmaf(A.x, wv0.x, fmaf(A.y, wv1.x, bbv.x)) + fmaf(A.z, wee.x, fmaf(xn.x, ws0.x, fmaf(xn.y, ws1.x, bbs.x)));
    r.y = fmaf(A.x, wv0.y, fmaf(A.y, wv1.y, bbv.y)) + fmaf(A.z, wee.y, fmaf(xn.x, ws0.y, fmaf(xn.y, ws1.y, bbs.y)));
    r.z = fmaf(A.x, wv0.z, fmaf(A.y, wv1.z, bbv.z)) + fmaf(A.z, wee.z, fmaf(xn.x, ws0.z, fmaf(xn.y, ws1.z, bbs.z)));
    r.w = fmaf(A.x, wv0.w, fmaf(A.y, wv1.w, bbv.w)) + fmaf(A.z, wee.w, fmaf(xn.x, ws0.w, fmaf(xn.y, ws1.w, bbs.w)));
    r.x = fmaxf(r.x, 0.f); r.y = fmaxf(r.y, 0.f);
    r.z = fmaxf(r.z, 0.f); r.w = fmaxf(r.w, 0.f);
    ((float4*)g_H0)[(size_t)n * 32 + c4] = r;
}

// ---------------- layer-1 projections: 3xTF32 tensor-core GEMM ----------------
#define SA 20     // A smem panel stride (16 + 4 pad)
#define SB 136    // B smem panel stride (128 + 8 pad)

__device__ __forceinline__ void split_tf32(float x, uint32_t& hi, uint32_t& lo) {
    uint32_t h;
    asm("cvt.rna.tf32.f32 %0, %1;" : "=r"(h) : "f"(x));
    float r = x - __uint_as_float(h);
    uint32_t l;
    asm("cvt.rna.tf32.f32 %0, %1;" : "=r"(l) : "f"(r));
    hi = h; lo = l;
}

__device__ __forceinline__ void mma8(float* c, const uint32_t* a, const uint32_t* b) {
    asm volatile(
        "mma.sync.aligned.m16n8k8.row.col.f32.tf32.tf32.f32 "
        "{%0,%1,%2,%3}, {%4,%5,%6,%7}, {%8,%9}, {%0,%1,%2,%3};"
        : "+f"(c[0]), "+f"(c[1]), "+f"(c[2]), "+f"(c[3])
        : "r"(a[0]), "r"(a[1]), "r"(a[2]), "r"(a[3]), "r"(b[0]), "r"(b[1]));
}

__global__ __launch_bounds__(256, 2) void gemm3_kernel(
    const float* __restrict__ Wq, const float* __restrict__ Wk,
    const float* __restrict__ Wv, const float* __restrict__ Ws,
    const float* __restrict__ bq, const float* __restrict__ bk,
    const float* __restrict__ bv, const float* __restrict__ bs) {
    __shared__ uint32_t AsH[128][SA];
    __shared__ uint32_t AsL[128][SA];
    __shared__ uint32_t BsH[16][SB];
    __shared__ uint32_t BsL[16][SB];

    const float* W; const float* bias;
    int sec = blockIdx.y;
    if (sec == 0)      { W = Wq; bias = bq; }
    else if (sec == 1) { W = Wk; bias = bk; }
    else if (sec == 2) { W = Wv; bias = bv; }
    else               { W = Ws; bias = bs; }

    int tid  = threadIdx.x;
    int warp = tid >> 5, lane = tid & 31;
    int g    = lane >> 2, tig = lane & 3;
    int wm   = warp >> 2, wn = warp & 3;         // 2 x 4 warp grid
    int blockM = blockIdx.x * 128;

    float acc[4][4][4];
#pragma unroll
    for (int mt = 0; mt < 4; mt++)
#pragma unroll
        for (int nt = 0; nt < 4; nt++)
#pragma unroll
            for (int c = 0; c < 4; c++) acc[mt][nt][c] = 0.f;

#pragma unroll 1
    for (int kp = 0; kp < 8; kp++) {
        int k0 = kp * 16;
        __syncthreads();
#pragma unroll
        for (int j = 0; j < 2; j++) {
            int pos = tid + 256 * j;
            int row = pos >> 2;
            int c4  = pos & 3;
            float4 v = *(const float4*)(g_H0 + (size_t)(blockM + row) * 128 + k0 + c4 * 4);
            uint4 h, l;
            split_tf32(v.x, h.x, l.x);
            split_tf32(v.y, h.y, l.y);
            split_tf32(v.z, h.z, l.z);
            split_tf32(v.w, h.w, l.w);
            *(uint4*)&AsH[row][c4 * 4] = h;
            *(uint4*)&AsL[row][c4 * 4] = l;
        }
#pragma unroll
        for (int j = 0; j < 2; j++) {
            int pos = tid + 256 * j;
            int row = pos >> 5;
            int c4  = pos & 31;
            float4 v = *(const float4*)(W + (size_t)(k0 + row) * 128 + c4 * 4);
            uint4 h, l;
            split_tf32(v.x, h.x, l.x);
            split_tf32(v.y, h.y, l.y);
            split_tf32(v.z, h.z, l.z);
            split_tf32(v.w, h.w, l.w);
            *(uint4*)&BsH[row][c4 * 4] = h;
            *(uint4*)&BsL[row][c4 * 4] = l;
        }
        __syncthreads();

#pragma unroll
        for (int ks = 0; ks < 2; ks++) {
            int kk = ks * 8;
            uint32_t bh[4][2], bl[4][2];
#pragma unroll
            for (int nt = 0; nt < 4; nt++) {
                int col = wn * 32 + nt * 8 + g;
                bh[nt][0] = BsH[kk + tig][col];
                bh[nt][1] = BsH[kk + tig + 4][col];
                bl[nt][0] = BsL[kk + tig][col];
                bl[nt][1] = BsL[kk + tig + 4][col];
            }
#pragma unroll
            for (int mt = 0; mt < 4; mt++) {
                int r0 = wm * 64 + mt * 16 + g;
                uint32_t ah[4], al[4];
                ah[0] = AsH[r0][kk + tig];
                ah[1] = AsH[r0 + 8][kk + tig];
                ah[2] = AsH[r0][kk + tig + 4];
                ah[3] = AsH[r0 + 8][kk + tig + 4];
                al[0] = AsL[r0][kk + tig];
                al[1] = AsL[r0 + 8][kk + tig];
                al[2] = AsL[r0][kk + tig + 4];
                al[3] = AsL[r0 + 8][kk + tig + 4];
#pragma unroll
                for (int nt = 0; nt < 4; nt++) {
                    mma8(acc[mt][nt], ah, bh[nt]);   // hi*hi
                    mma8(acc[mt][nt], ah, bl[nt]);   // hi*lo
                    mma8(acc[mt][nt], al, bh[nt]);   // lo*hi
                }
            }
        }
    }

    // epilogue: q -> P cols 0..127; s -> P cols 128..255; k/v -> fp16 KV only
    bool isKV = (sec == 1 || sec == 2);
    int kvOff = (sec == 2) ? 64 : 0;
    int pOff  = (sec == 3) ? 128 : 0;
#pragma unroll
    for (int mt = 0; mt < 4; mt++) {
        int r0 = blockM + wm * 64 + mt * 16 + g;
#pragma unroll
        for (int nt = 0; nt < 4; nt++) {
            int cn = wn * 32 + nt * 8 + tig * 2;
            float b0 = bias[cn], b1 = bias[cn + 1];
            float2 v0 = make_float2(acc[mt][nt][0] + b0, acc[mt][nt][1] + b1);
            float2 v1 = make_float2(acc[mt][nt][2] + b0, acc[mt][nt][3] + b1);
            if (isKV) {
                g_KV[(size_t)r0 * 128 + kvOff + cn / 2]       = __floats2half2_rn(v0.x, v0.y);
                g_KV[(size_t)(r0 + 8) * 128 + kvOff + cn / 2] = __floats2half2_rn(v1.x, v1.y);
            } else {
                *(float2*)(g_P + (size_t)r0 * PW + pOff + cn)       = v0;
                *(float2*)(g_P + (size_t)(r0 + 8) * PW + pOff + cn) = v1;
            }
        }
    }
}

// ---------------- layer-1 edge attention: warp/node, dual-state online softmax ----------------
__device__ __forceinline__ float4 ldg_kv4(const __half2* p) {
    uint2 r = __ldg((const uint2*)p);
    __half2 h0 = *reinterpret_cast<__half2*>(&r.x);
    __half2 h1 = *reinterpret_cast<__half2*>(&r.y);
    float2 a = __half22float2(h0);
    float2 b = __half22float2(h1);
    return make_float4(a.x, a.y, b.x, b.y);
}

__device__ __forceinline__ float dot_reduce16(float4 q, float4 k) {
    float part = q.x * k.x + q.y * k.y + q.z * k.z + q.w * k.w;
    part += __shfl_xor_sync(0xffffffffu, part, 8, 16);
    part += __shfl_xor_sync(0xffffffffu, part, 4, 16);
    part += __shfl_xor_sync(0xffffffffu, part, 2, 16);
    part += __shfl_xor_sync(0xffffffffu, part, 1, 16);
    return part;
}

__global__ void attn_kernel(const float* __restrict__ We, int N) {
    int gt   = blockIdx.x * blockDim.x + threadIdx.x;
    int lane = threadIdx.x & 31;
    int n    = gt >> 5;
    if (n >= N) return;

    const float4* P4 = (const float4*)g_P;
    size_t base = (size_t)n * 64;
    float4 qv = __ldg(P4 + base + lane);
    float4 we = __ldg(((const float4*)We) + lane);
    float qWe = dot_reduce16(qv, we);    // per-head scalar

    float4 accA = make_float4(0.f, 0.f, 0.f, 0.f);
    float4 accB = make_float4(0.f, 0.f, 0.f, 0.f);
    float mA = -1e30f, mB = -1e30f;
    float dA = 0.f,    dB = 0.f;
    float sA = 0.f,    sB = 0.f;         // Sum ex * attr

    int beg = g_rowptr[n], end = g_rowptr[n + 1];
    int i = beg;
    for (; i + 1 < end; i += 2) {
        int   s0 = __ldg(g_src + i);
        int   s1 = __ldg(g_src + i + 1);
        float a0 = __ldg(g_attr + i);
        float a1 = __ldg(g_attr + i + 1);
        const __half2* kv0 = g_KV + (size_t)s0 * 128 + lane * 2;
        const __half2* kv1 = g_KV + (size_t)s1 * 128 + lane * 2;

        float4 k0 = ldg_kv4(kv0);
        float4 k1 = ldg_kv4(kv1);
        float4 v0 = ldg_kv4(kv0 + 64);
        float4 v1 = ldg_kv4(kv1 + 64);

        float l0 = (dot_reduce16(qv, k0) + a0 * qWe) * 0.125f;
        float l1 = (dot_reduce16(qv, k1) + a1 * qWe) * 0.125f;

        {
            float nm = fmaxf(mA, l0);
            float sc = __expf(mA - nm);
            float ex = __expf(l0 - nm);
            accA.x = fmaf(accA.x, sc, ex * v0.x);
            accA.y = fmaf(accA.y, sc, ex * v0.y);
            accA.z = fmaf(accA.z, sc, ex * v0.z);
            accA.w = fmaf(accA.w, sc, ex * v0.w);
            dA = fmaf(dA, sc, ex);
            sA = fmaf(sA, sc, ex * a0);
            mA = nm;
        }
        {
            float nm = fmaxf(mB, l1);
            float sc = __expf(mB - nm);
            float ex = __expf(l1 - nm);
            accB.x = fmaf(accB.x, sc, ex * v1.x);
            accB.y = fmaf(accB.y, sc, ex * v1.y);
            accB.z = fmaf(accB.z, sc, ex * v1.z);
            accB.w = fmaf(accB.w, sc, ex * v1.w);
            dB = fmaf(dB, sc, ex);
            sB = fmaf(sB, sc, ex * a1);
            mB = nm;
        }
    }
    if (i < end) {   // odd tail -> state A
        int   s0 = __ldg(g_src + i);
        float a0 = __ldg(g_attr + i);
        const __half2* kv0 = g_KV + (size_t)s0 * 128 + lane * 2;
        float4 k0 = ldg_kv4(kv0);
        float4 v0 = ldg_kv4(kv0 + 64);
        float l0 = (dot_reduce16(qv, k0) + a0 * qWe) * 0.125f;
        float nm = fmaxf(mA, l0);
        float sc = __expf(mA - nm);
        float ex = __expf(l0 - nm);
        accA.x = fmaf(accA.x, sc, ex * v0.x);
        accA.y = fmaf(accA.y, sc, ex * v0.y);
        accA.z = fmaf(accA.z, sc, ex * v0.z);
        accA.w = fmaf(accA.w, sc, ex * v0.w);
        dA = fmaf(dA, sc, ex);
        sA = fmaf(sA, sc, ex * a0);
        mA = nm;
    }

    // exact merge
    float nm = fmaxf(mA, mB);
    float eA = __expf(mA - nm);
    float eB = __expf(mB - nm);
    float den  = dA * eA + dB * eB;
    float sSum = sA * eA + sB * eB;
    float4 acc;
    acc.x = fmaf(accA.x, eA, accB.x * eB);
    acc.y = fmaf(accA.y, eA, accB.y * eB);
    acc.z = fmaf(accA.z, eA, accB.z * eB);
    acc.w = fmaf(accA.w, eA, accB.w * eB);
    acc.x = fmaf(sSum, we.x, acc.x);
    acc.y = fmaf(sSum, we.y, acc.y);
    acc.z = fmaf(sSum, we.z, acc.z);
    acc.w = fmaf(sSum, we.w, acc.w);

    float inv = 1.f / (den + 1e-16f);
    float4 sk = __ldg(P4 + base + 32 + lane);
    float4 o;
    o.x = fmaxf(fmaf(acc.x, inv, sk.x), 0.f);
    o.y = fmaxf(fmaf(acc.y, inv, sk.y), 0.f);
    o.z = fmaxf(fmaf(acc.z, inv, sk.z), 0.f);
    o.w = fmaxf(fmaf(acc.w, inv, sk.w), 0.f);
    ((float4*)g_H1)[(size_t)n * 32 + lane] = o;
}

// ---------------- graph mean pool, two-stage (batch is sorted) ----------------
__global__ void pool_kernel() {
    int g = blockIdx.x;
    int c = blockIdx.y;          // 0..7 partial
    int t = threadIdx.x;
    int b0 = g_gstart[g], b1 = g_gstart[g + 1];
    int len = b1 - b0;
    int chunk = (len + 7) >> 3;
    int lo = b0 + c * chunk;
    int hi = min(lo + chunk, b1);
    float acc = 0.f;
#pragma unroll 4
    for (int n = lo; n < hi; n++) acc += g_H1[(size_t)n * HD + t];
    g_poolp[((size_t)g * 8 + c) * HD + t] = acc;
}

// ---------------- classifier head (folds pool reduction) ----------------
__global__ void classifier_kernel(const float* __restrict__ cW1, const float* __restrict__ cb1,
                                  const float* __restrict__ cW2, const float* __restrict__ cb2,
                                  float* __restrict__ out) {
    __shared__ float gs[HD];
    __shared__ float hid[HD];
    int g = blockIdx.x;
    int t = threadIdx.x;
    float s = 0.f;
#pragma unroll
    for (int c = 0; c < 8; c++) s += g_poolp[((size_t)g * 8 + c) * HD + t];
    float cnt = (float)max(g_gstart[g + 1] - g_gstart[g], 1);
    gs[t] = s / cnt;
    __syncthreads();
    float acc = cb1[t];
#pragma unroll 8
    for (int c = 0; c < HD; c++) acc = fmaf(gs[c], cW1[c * 128 + t], acc);
    hid[t] = fmaxf(acc, 0.f);
    __syncthreads();
    if (t < 30) {
        float o = cb2[t];
#pragma unroll 8
        for (int j = 0; j < HD; j++) o = fmaf(hid[j], cW2[j * 30 + t], o);
        out[g * 30 + t] = o;
    }
}

// ---------------- launch ----------------
extern "C" void kernel_launch(void* const* d_in, const int* in_sizes, int n_in,
                              void* d_out, int out_size) {
    const float* x      = (const float*)d_in[0];
    const int*   ei     = (const int*)d_in[1];
    const float* eattr  = (const float*)d_in[2];
    const int*   batch  = (const int*)d_in[3];
    const float* l0_Wq = (const float*)d_in[4];
    const float* l0_bq = (const float*)d_in[5];
    const float* l0_Wk = (const float*)d_in[6];
    const float* l0_bk = (const float*)d_in[7];
    const float* l0_Wv = (const float*)d_in[8];
    const float* l0_bv = (const float*)d_in[9];
    const float* l0_We = (const float*)d_in[10];
    const float* l0_Ws = (const float*)d_in[11];
    const float* l0_bs = (const float*)d_in[12];
    const float* l1_Wq = (const float*)d_in[13];
    const float* l1_bq = (const float*)d_in[14];
    const float* l1_Wk = (const float*)d_in[15];
    const float* l1_bk = (const float*)d_in[16];
    const float* l1_Wv = (const float*)d_in[17];
    const float* l1_bv = (const float*)d_in[18];
    const float* l1_We = (const float*)d_in[19];
    const float* l1_Ws = (const float*)d_in[20];
    const float* l1_bs = (const float*)d_in[21];
    const float* cW1   = (const float*)d_in[22];
    const float* cb1   = (const float*)d_in[23];
    const float* cW2   = (const float*)d_in[24];
    const float* cb2   = (const float*)d_in[25];
    float* out = (float*)d_out;

    int N = in_sizes[3];       // batch length = #nodes
    int E = in_sizes[2];       // edge_attr length = #edges
    const int* src = ei;
    const int* dst = ei + E;

    // CSR build (reused by both layers)
    zero_kernel<<<(N + 255) / 256, 256>>>(N);
    hist_kernel<<<(E + 255) / 256, 256>>>(dst, batch, N, E);
    scan_kernel<<<1, 1024>>>(N);
    scatter_kernel<<<(E + 255) / 256, 256>>>(src, dst, eattr, E);

    // layer 0: algebraically collapsed (in_ch = 2)
    prep0_kernel<<<1, 32>>>(l0_Wq, l0_bq, l0_Wk, l0_bk, l0_We);
    attn0_kernel<<<(N + 127) / 128, 128>>>(x, N);
    expand0_kernel<<<(N * 32 + 255) / 256, 256>>>(x, l0_Wv, l0_bv, l0_We, l0_Ws, l0_bs, N);

    // layer 1 projections: fused 3xTF32 tensor-core GEMM, all 4 weights
    dim3 ggrid((N + 127) / 128, 4);
    gemm3_kernel<<<ggrid, 256>>>(l1_Wq, l1_Wk, l1_Wv, l1_Ws,
                                 l1_bq, l1_bk, l1_bv, l1_bs);

    attn_kernel<<<(N * 32 + 255) / 256, 256>>>(l1_We, N);

    // pool (two-stage) + head
    dim3 pgrid(GMAX, 8);
    pool_kernel<<<pgrid, HD>>>();
    classifier_kernel<<<GMAX, HD>>>(cW1, cb1, cW2, cb2, out);
}

// round 7
// speedup vs baseline: 1.6003x; 1.1486x over previous
#include <cuda_runtime.h>
#include <cuda_fp16.h>
#include <cstdint>

// ---------------- problem constants ----------------
#define NMAX   50048      // padded node capacity
#define EMAX   800000
#define GMAX   64
#define HD     128        // hidden dim (H*D)
#define PW     256        // q|skip packed row width for layer 1

// ---------------- static scratch (no allocs allowed) ----------------
__device__ float   g_P[(size_t)NMAX * PW];    // layer1 packed q|s (fp32)
__device__ __half2 g_KV[(size_t)NMAX * 128];  // layer1 per node: k | v (fp16)
__device__ float   g_H0[(size_t)NMAX * HD];   // layer0 output (post relu)
__device__ float   g_H1[(size_t)NMAX * HD];   // layer1 output (post relu)
__device__ float   g_A[(size_t)NMAX * 8];     // layer0 compact attn results
__device__ float   g_M0[18];                  // layer0 3x3 bilinear forms (2 heads)
__device__ float   g_cq0[6];                  // layer0 q.We coefficient 3-vectors
__device__ int     g_deg[NMAX];
__device__ int     g_cnt[NMAX];
__device__ int     g_rowptr[NMAX + 1];
__device__ int     g_src[EMAX];
__device__ float   g_attr[EMAX];
__device__ int     g_ghist[GMAX];
__device__ int     g_gstart[GMAX + 1];
__device__ float   g_poolp[GMAX * 8 * HD];    // partial pool sums

// ---------------- CSR build ----------------
__global__ void zero_kernel(int N) {
    int i = blockIdx.x * blockDim.x + threadIdx.x;
    if (i < N) { g_deg[i] = 0; g_cnt[i] = 0; }
    if (i < GMAX) g_ghist[i] = 0;
}

__global__ void hist_kernel(const int* __restrict__ dst,
                            const int* __restrict__ batch, int N, int E) {
    int i = blockIdx.x * blockDim.x + threadIdx.x;
    if (i < E) atomicAdd(&g_deg[dst[i]], 1);
    if (i < N) atomicAdd(&g_ghist[batch[i]], 1);
}

__global__ void scan_kernel(int N) {
    __shared__ int sums[1024];
    int t = threadIdx.x;
    int chunk = (N + 1023) >> 10;
    chunk = (chunk + 3) & ~3;                  // int4-aligned chunks
    int lo = t * chunk;
    int hi = min(lo + chunk, N);
    int s = 0;
    int i = lo;
    for (; i + 4 <= hi; i += 4) {              // vectorized degree sum
        int4 v = *(const int4*)(g_deg + i);
        s += v.x + v.y + v.z + v.w;
    }
    for (; i < hi; i++) s += g_deg[i];
    sums[t] = s;
    __syncthreads();
    for (int off = 1; off < 1024; off <<= 1) {
        int v = (t >= off) ? sums[t - off] : 0;
        __syncthreads();
        sums[t] += v;
        __syncthreads();
    }
    int run = sums[t] - s;   // exclusive prefix
    for (int j = lo; j < hi; j++) { g_rowptr[j] = run; run += g_deg[j]; }
    if (t == 1023) g_rowptr[N] = sums[1023];
    if (t == 0) {
        int r = 0;
        for (int g = 0; g < GMAX; g++) { g_gstart[g] = r; r += g_ghist[g]; }
        g_gstart[GMAX] = r;
    }
}

__global__ void scatter_kernel(const int* __restrict__ src,
                               const int* __restrict__ dst,
                               const float* __restrict__ attr, int E) {
    int i = blockIdx.x * blockDim.x + threadIdx.x;
    if (i >= E) return;
    int d = dst[i];
    int p = g_rowptr[d] + atomicAdd(&g_cnt[d], 1);
    g_src[p]  = src[i];
    g_attr[p] = attr[i];
}

// ---------------- layer-0 precompute: 3x3 bilinear forms ----------------
__global__ void prep0_kernel(const float* __restrict__ Wq, const float* __restrict__ bq,
                             const float* __restrict__ Wk, const float* __restrict__ bk,
                             const float* __restrict__ We) {
    int t = threadIdx.x;
    if (t < 18) {
        int h = t / 9, rem = t % 9, r = rem / 3, c = rem % 3;
        const float* qrow = (r < 2) ? (Wq + r * 128 + h * 64) : (bq + h * 64);
        const float* krow = (c < 2) ? (Wk + c * 128 + h * 64) : (bk + h * 64);
        float s = 0.f;
#pragma unroll 8
        for (int d = 0; d < 64; d++) s += qrow[d] * krow[d];
        g_M0[t] = s;
    } else if (t < 24) {
        int j = t - 18;
        int h = j / 3, r = j % 3;
        const float* qrow = (r < 2) ? (Wq + r * 128 + h * 64) : (bq + h * 64);
        const float* we = We + h * 64;
        float s = 0.f;
#pragma unroll 8
        for (int d = 0; d < 64; d++) s += qrow[d] * we[d];
        g_cq0[j] = s;
    }
}

// ---------------- layer-0 attention: one THREAD per node ----------------
__global__ void attn0_kernel(const float* __restrict__ x, int N) {
    __shared__ float sM[18], sC[6];
    int t = threadIdx.x;
    if (t < 18) sM[t] = g_M0[t];
    if (t < 6)  sC[t] = g_cq0[t];
    __syncthreads();

    int n = blockIdx.x * blockDim.x + t;
    if (n >= N) return;

    const float2* x2 = (const float2*)x;
    float2 xd = __ldg(x2 + n);

    float w[2][3], cqd[2];
#pragma unroll
    for (int h = 0; h < 2; h++) {
#pragma unroll
        for (int j = 0; j < 3; j++)
            w[h][j] = fmaf(xd.x, sM[h * 9 + j], fmaf(xd.y, sM[h * 9 + 3 + j], sM[h * 9 + 6 + j]));
        cqd[h] = fmaf(xd.x, sC[h * 3], fmaf(xd.y, sC[h * 3 + 1], sC[h * 3 + 2]));
    }

    float m[2]   = {-1e30f, -1e30f};
    float den[2] = {0.f, 0.f};
    float S0[2]  = {0.f, 0.f};
    float S1[2]  = {0.f, 0.f};
    float Sa[2]  = {0.f, 0.f};

    int beg = g_rowptr[n], end = g_rowptr[n + 1];
    int sNxt = 0; float aNxt = 0.f; float2 xsNxt = make_float2(0.f, 0.f);
    if (beg < end) {
        sNxt = __ldg(g_src + beg);
        aNxt = __ldg(g_attr + beg);
        xsNxt = __ldg(x2 + sNxt);
    }
    for (int i = beg; i < end; i++) {
        float a = aNxt; float2 xs = xsNxt;
        if (i + 1 < end) {
            sNxt = __ldg(g_src + i + 1);
            aNxt = __ldg(g_attr + i + 1);
            xsNxt = __ldg(x2 + sNxt);
        }
#pragma unroll
        for (int h = 0; h < 2; h++) {
            float l = fmaf(a, cqd[h],
                      fmaf(xs.x, w[h][0], fmaf(xs.y, w[h][1], w[h][2]))) * 0.125f;
            float nm = fmaxf(m[h], l);
            float sc = __expf(m[h] - nm);
            float ex = __expf(l - nm);
            S0[h] = fmaf(S0[h], sc, ex * xs.x);
            S1[h] = fmaf(S1[h], sc, ex * xs.y);
            Sa[h] = fmaf(Sa[h], sc, ex * a);
            den[h] = fmaf(den[h], sc, ex);
            m[h] = nm;
        }
    }

    float4* A4 = (float4*)g_A;
#pragma unroll
    for (int h = 0; h < 2; h++) {
        float inv = 1.f / (den[h] + 1e-16f);
        A4[(size_t)n * 2 + h] = make_float4(S0[h] * inv, S1[h] * inv, Sa[h] * inv, 0.f);
    }
}

// ---------------- layer-0 expansion ----------------
__global__ void expand0_kernel(const float* __restrict__ x,
                               const float* __restrict__ Wv, const float* __restrict__ bv,
                               const float* __restrict__ We,
                               const float* __restrict__ Ws, const float* __restrict__ bs,
                               int N) {
    int idx = blockIdx.x * blockDim.x + threadIdx.x;
    if (idx >= N * 32) return;
    int n  = idx >> 5;
    int c4 = idx & 31;
    int h  = c4 >> 4;
    int cc = c4 * 4;

    float4 wv0 = *(const float4*)(Wv + cc);
    float4 wv1 = *(const float4*)(Wv + 128 + cc);
    float4 bbv = *(const float4*)(bv + cc);
    float4 wee = *(const float4*)(We + cc);
    float4 ws0 = *(const float4*)(Ws + cc);
    float4 ws1 = *(const float4*)(Ws + 128 + cc);
    float4 bbs = *(const float4*)(bs + cc);

    float2 xn = __ldg((const float2*)x + n);
    float4 A  = __ldg(((const float4*)g_A) + (size_t)n * 2 + h);

    float4 r;
    r.x = fmaf(A.x, wv0.x, fmaf(A.y, wv1.x, bbv.x)) + fmaf(A.z, wee.x, fmaf(xn.x, ws0.x, fmaf(xn.y, ws1.x, bbs.x)));
    r.y = fmaf(A.x, wv0.y, fmaf(A.y, wv1.y, bbv.y)) + fmaf(A.z, wee.y, fmaf(xn.x, ws0.y, fmaf(xn.y, ws1.y, bbs.y)));
    r.z = fmaf(A.x, wv0.z, fmaf(A.y, wv1.z, bbv.z)) + fmaf(A.z, wee.z, fmaf(xn.x, ws0.z, fmaf(xn.y, ws1.z, bbs.z)));
    r.w = fmaf(A.x, wv0.w, fmaf(A.y, wv1.w, bbv.w)) + fmaf(A.z, wee.w, fmaf(xn.x, ws0.w, fmaf(xn.y, ws1.w, bbs.w)));
    r.x = fmaxf(r.x, 0.f); r.y = fmaxf(r.y, 0.f);
    r.z = fmaxf(r.z, 0.f); r.w = fmaxf(r.w, 0.f);
    ((float4*)g_H0)[(size_t)n * 32 + c4] = r;
}

// ---------------- layer-1 projections: 3-pass fp16-split m16n8k16 GEMM ----------------
#define PA 10     // A half2 row stride (8 + 2 pad)
#define PB 9      // B half2 col stride (8 + 1 pad)

__device__ __forceinline__ void split_f16(float x, __half& h, __half& l) {
    h = __float2half_rn(x);
    l = __float2half_rn(x - __half2float(h));
}
__device__ __forceinline__ uint32_t pack2(__half a, __half b) {
    __half2 t = __halves2half2(a, b);
    return *reinterpret_cast<uint32_t*>(&t);
}

__device__ __forceinline__ void mma16(float* c, const uint32_t* a, const uint32_t* b) {
    asm volatile(
        "mma.sync.aligned.m16n8k16.row.col.f32.f16.f16.f32 "
        "{%0,%1,%2,%3}, {%4,%5,%6,%7}, {%8,%9}, {%0,%1,%2,%3};"
        : "+f"(c[0]), "+f"(c[1]), "+f"(c[2]), "+f"(c[3])
        : "r"(a[0]), "r"(a[1]), "r"(a[2]), "r"(a[3]), "r"(b[0]), "r"(b[1]));
}

__global__ __launch_bounds__(256, 2) void gemm3_kernel(
    const float* __restrict__ Wq, const float* __restrict__ Wk,
    const float* __restrict__ Wv, const float* __restrict__ Ws,
    const float* __restrict__ bq, const float* __restrict__ bk,
    const float* __restrict__ bv, const float* __restrict__ bs) {
    __shared__ uint32_t AsH[128 * PA];
    __shared__ uint32_t AsL[128 * PA];
    __shared__ uint32_t BsH[128 * PB];
    __shared__ uint32_t BsL[128 * PB];

    const float* W; const float* bias;
    int sec = blockIdx.y;
    if (sec == 0)      { W = Wq; bias = bq; }
    else if (sec == 1) { W = Wk; bias = bk; }
    else if (sec == 2) { W = Wv; bias = bv; }
    else               { W = Ws; bias = bs; }

    int tid  = threadIdx.x;
    int warp = tid >> 5, lane = tid & 31;
    int g    = lane >> 2, tig = lane & 3;
    int wm   = warp >> 2, wn = warp & 3;         // 2 x 4 warp grid
    int blockM = blockIdx.x * 128;

    float acc[4][4][4];
#pragma unroll
    for (int mt = 0; mt < 4; mt++)
#pragma unroll
        for (int nt = 0; nt < 4; nt++)
#pragma unroll
            for (int c = 0; c < 4; c++) acc[mt][nt][c] = 0.f;

    int bkp = tid >> 5;          // B loader: k-pair 0..7
    int bc4 = tid & 31;          // B loader: col group (4 cols)

#pragma unroll 1
    for (int kp8 = 0; kp8 < 8; kp8++) {
        int k0 = kp8 * 16;
        __syncthreads();
        // A panel: 128 rows x 16 k (fp16 hi/lo, packed k-pairs)
#pragma unroll
        for (int j = 0; j < 2; j++) {
            int pos = tid + 256 * j;
            int row = pos >> 2;
            int c4  = pos & 3;
            float4 v = *(const float4*)(g_H0 + (size_t)(blockM + row) * 128 + k0 + c4 * 4);
            __half hx, lx, hy, ly, hz, lz, hw, lw;
            split_f16(v.x, hx, lx); split_f16(v.y, hy, ly);
            split_f16(v.z, hz, lz); split_f16(v.w, hw, lw);
            AsH[row * PA + c4 * 2]     = pack2(hx, hy);
            AsH[row * PA + c4 * 2 + 1] = pack2(hz, hw);
            AsL[row * PA + c4 * 2]     = pack2(lx, ly);
            AsL[row * PA + c4 * 2 + 1] = pack2(lz, lw);
        }
        // B panel: 16 k x 128 cols -> col-major half2 k-pairs
        {
            const float* wp = W + (size_t)(k0 + 2 * bkp) * 128 + bc4 * 4;
            float4 r0 = *(const float4*)wp;
            float4 r1 = *(const float4*)(wp + 128);
            const float* f0 = &r0.x;
            const float* f1 = &r1.x;
#pragma unroll
            for (int j = 0; j < 4; j++) {
                __half h0, l0, h1, l1;
                split_f16(f0[j], h0, l0);
                split_f16(f1[j], h1, l1);
                int col = bc4 * 4 + j;
                BsH[col * PB + bkp] = pack2(h0, h1);
                BsL[col * PB + bkp] = pack2(l0, l1);
            }
        }
        __syncthreads();

        uint32_t bh[4][2], bl[4][2];
#pragma unroll
        for (int nt = 0; nt < 4; nt++) {
            int col = wn * 32 + nt * 8 + g;
            bh[nt][0] = BsH[col * PB + tig];
            bh[nt][1] = BsH[col * PB + tig + 4];
            bl[nt][0] = BsL[col * PB + tig];
            bl[nt][1] = BsL[col * PB + tig + 4];
        }
#pragma unroll
        for (int mt = 0; mt < 4; mt++) {
            int r0 = wm * 64 + mt * 16 + g;
            uint32_t ah[4], al[4];
            ah[0] = AsH[r0 * PA + tig];
            ah[1] = AsH[(r0 + 8) * PA + tig];
            ah[2] = AsH[r0 * PA + tig + 4];
            ah[3] = AsH[(r0 + 8) * PA + tig + 4];
            al[0] = AsL[r0 * PA + tig];
            al[1] = AsL[(r0 + 8) * PA + tig];
            al[2] = AsL[r0 * PA + tig + 4];
            al[3] = AsL[(r0 + 8) * PA + tig + 4];
#pragma unroll
            for (int nt = 0; nt < 4; nt++) {
                mma16(acc[mt][nt], ah, bh[nt]);   // hi*hi
                mma16(acc[mt][nt], ah, bl[nt]);   // hi*lo
                mma16(acc[mt][nt], al, bh[nt]);   // lo*hi
            }
        }
    }

    // epilogue: q -> P cols 0..127; s -> P cols 128..255; k/v -> fp16 KV only
    bool isKV = (sec == 1 || sec == 2);
    int kvOff = (sec == 2) ? 64 : 0;
    int pOff  = (sec == 3) ? 128 : 0;
#pragma unroll
    for (int mt = 0; mt < 4; mt++) {
        int r0 = blockM + wm * 64 + mt * 16 + g;
#pragma unroll
        for (int nt = 0; nt < 4; nt++) {
            int cn = wn * 32 + nt * 8 + tig * 2;
            float b0 = bias[cn], b1 = bias[cn + 1];
            float2 v0 = make_float2(acc[mt][nt][0] + b0, acc[mt][nt][1] + b1);
            float2 v1 = make_float2(acc[mt][nt][2] + b0, acc[mt][nt][3] + b1);
            if (isKV) {
                g_KV[(size_t)r0 * 128 + kvOff + cn / 2]       = __floats2half2_rn(v0.x, v0.y);
                g_KV[(size_t)(r0 + 8) * 128 + kvOff + cn / 2] = __floats2half2_rn(v1.x, v1.y);
            } else {
                *(float2*)(g_P + (size_t)r0 * PW + pOff + cn)       = v0;
                *(float2*)(g_P + (size_t)(r0 + 8) * PW + pOff + cn) = v1;
            }
        }
    }
}

// ---------------- layer-1 edge attention: warp/node, dual-state online softmax ----------------
__device__ __forceinline__ float4 ldg_kv4(const __half2* p) {
    uint2 r = __ldg((const uint2*)p);
    __half2 h0 = *reinterpret_cast<__half2*>(&r.x);
    __half2 h1 = *reinterpret_cast<__half2*>(&r.y);
    float2 a = __half22float2(h0);
    float2 b = __half22float2(h1);
    return make_float4(a.x, a.y, b.x, b.y);
}

__device__ __forceinline__ float dot_reduce16(float4 q, float4 k) {
    float part = q.x * k.x + q.y * k.y + q.z * k.z + q.w * k.w;
    part += __shfl_xor_sync(0xffffffffu, part, 8, 16);
    part += __shfl_xor_sync(0xffffffffu, part, 4, 16);
    part += __shfl_xor_sync(0xffffffffu, part, 2, 16);
    part += __shfl_xor_sync(0xffffffffu, part, 1, 16);
    return part;
}

__global__ void attn_kernel(const float* __restrict__ We, int N) {
    int gt   = blockIdx.x * blockDim.x + threadIdx.x;
    int lane = threadIdx.x & 31;
    int n    = gt >> 5;
    if (n >= N) return;

    const float4* P4 = (const float4*)g_P;
    size_t base = (size_t)n * 64;
    float4 qv = __ldg(P4 + base + lane);
    float4 we = __ldg(((const float4*)We) + lane);
    float qWe = dot_reduce16(qv, we);

    float4 accA = make_float4(0.f, 0.f, 0.f, 0.f);
    float4 accB = make_float4(0.f, 0.f, 0.f, 0.f);
    float mA = -1e30f, mB = -1e30f;
    float dA = 0.f,    dB = 0.f;
    float sA = 0.f,    sB = 0.f;

    int beg = g_rowptr[n], end = g_rowptr[n + 1];
    int i = beg;
    for (; i + 1 < end; i += 2) {
        int   s0 = __ldg(g_src + i);
        int   s1 = __ldg(g_src + i + 1);
        float a0 = __ldg(g_attr + i);
        float a1 = __ldg(g_attr + i + 1);
        const __half2* kv0 = g_KV + (size_t)s0 * 128 + lane * 2;
        const __half2* kv1 = g_KV + (size_t)s1 * 128 + lane * 2;

        float4 k0 = ldg_kv4(kv0);
        float4 k1 = ldg_kv4(kv1);
        float4 v0 = ldg_kv4(kv0 + 64);
        float4 v1 = ldg_kv4(kv1 + 64);

        float l0 = (dot_reduce16(qv, k0) + a0 * qWe) * 0.125f;
        float l1 = (dot_reduce16(qv, k1) + a1 * qWe) * 0.125f;

        {
            float nm = fmaxf(mA, l0);
            float sc = __expf(mA - nm);
            float ex = __expf(l0 - nm);
            accA.x = fmaf(accA.x, sc, ex * v0.x);
            accA.y = fmaf(accA.y, sc, ex * v0.y);
            accA.z = fmaf(accA.z, sc, ex * v0.z);
            accA.w = fmaf(accA.w, sc, ex * v0.w);
            dA = fmaf(dA, sc, ex);
            sA = fmaf(sA, sc, ex * a0);
            mA = nm;
        }
        {
            float nm = fmaxf(mB, l1);
            float sc = __expf(mB - nm);
            float ex = __expf(l1 - nm);
            accB.x = fmaf(accB.x, sc, ex * v1.x);
            accB.y = fmaf(accB.y, sc, ex * v1.y);
            accB.z = fmaf(accB.z, sc, ex * v1.z);
            accB.w = fmaf(accB.w, sc, ex * v1.w);
            dB = fmaf(dB, sc, ex);
            sB = fmaf(sB, sc, ex * a1);
            mB = nm;
        }
    }
    if (i < end) {
        int   s0 = __ldg(g_src + i);
        float a0 = __ldg(g_attr + i);
        const __half2* kv0 = g_KV + (size_t)s0 * 128 + lane * 2;
        float4 k0 = ldg_kv4(kv0);
        float4 v0 = ldg_kv4(kv0 + 64);
        float l0 = (dot_reduce16(qv, k0) + a0 * qWe) * 0.125f;
        float nm = fmaxf(mA, l0);
        float sc = __expf(mA - nm);
        float ex = __expf(l0 - nm);
        accA.x = fmaf(accA.x, sc, ex * v0.x);
        accA.y = fmaf(accA.y, sc, ex * v0.y);
        accA.z = fmaf(accA.z, sc, ex * v0.z);
        accA.w = fmaf(accA.w, sc, ex * v0.w);
        dA = fmaf(dA, sc, ex);
        sA = fmaf(sA, sc, ex * a0);
        mA = nm;
    }

    float nm = fmaxf(mA, mB);
    float eA = __expf(mA - nm);
    float eB = __expf(mB - nm);
    float den  = dA * eA + dB * eB;
    float sSum = sA * eA + sB * eB;
    float4 acc;
    acc.x = fmaf(accA.x, eA, accB.x * eB);
    acc.y = fmaf(accA.y, eA, accB.y * eB);
    acc.z = fmaf(accA.z, eA, accB.z * eB);
    acc.w = fmaf(accA.w, eA, accB.w * eB);
    acc.x = fmaf(sSum, we.x, acc.x);
    acc.y = fmaf(sSum, we.y, acc.y);
    acc.z = fmaf(sSum, we.z, acc.z);
    acc.w = fmaf(sSum, we.w, acc.w);

    float inv = 1.f / (den + 1e-16f);
    float4 sk = __ldg(P4 + base + 32 + lane);
    float4 o;
    o.x = fmaxf(fmaf(acc.x, inv, sk.x), 0.f);
    o.y = fmaxf(fmaf(acc.y, inv, sk.y), 0.f);
    o.z = fmaxf(fmaf(acc.z, inv, sk.z), 0.f);
    o.w = fmaxf(fmaf(acc.w, inv, sk.w), 0.f);
    ((float4*)g_H1)[(size_t)n * 32 + lane] = o;
}

// ---------------- graph mean pool, two-stage ----------------
__global__ void pool_kernel() {
    int g = blockIdx.x;
    int c = blockIdx.y;
    int t = threadIdx.x;
    int b0 = g_gstart[g], b1 = g_gstart[g + 1];
    int len = b1 - b0;
    int chunk = (len + 7) >> 3;
    int lo = b0 + c * chunk;
    int hi = min(lo + chunk, b1);
    float acc = 0.f;
#pragma unroll 4
    for (int n = lo; n < hi; n++) acc += g_H1[(size_t)n * HD + t];
    g_poolp[((size_t)g * 8 + c) * HD + t] = acc;
}

// ---------------- classifier head ----------------
__global__ void classifier_kernel(const float* __restrict__ cW1, const float* __restrict__ cb1,
                                  const float* __restrict__ cW2, const float* __restrict__ cb2,
                                  float* __restrict__ out) {
    __shared__ float gs[HD];
    __shared__ float hid[HD];
    int g = blockIdx.x;
    int t = threadIdx.x;
    float s = 0.f;
#pragma unroll
    for (int c = 0; c < 8; c++) s += g_poolp[((size_t)g * 8 + c) * HD + t];
    float cnt = (float)max(g_gstart[g + 1] - g_gstart[g], 1);
    gs[t] = s / cnt;
    __syncthreads();
    float acc = cb1[t];
#pragma unroll 8
    for (int c = 0; c < HD; c++) acc = fmaf(gs[c], cW1[c * 128 + t], acc);
    hid[t] = fmaxf(acc, 0.f);
    __syncthreads();
    if (t < 30) {
        float o = cb2[t];
#pragma unroll 8
        for (int j = 0; j < HD; j++) o = fmaf(hid[j], cW2[j * 30 + t], o);
        out[g * 30 + t] = o;
    }
}

// ---------------- launch ----------------
extern "C" void kernel_launch(void* const* d_in, const int* in_sizes, int n_in,
                              void* d_out, int out_size) {
    const float* x      = (const float*)d_in[0];
    const int*   ei     = (const int*)d_in[1];
    const float* eattr  = (const float*)d_in[2];
    const int*   batch  = (const int*)d_in[3];
    const float* l0_Wq = (const float*)d_in[4];
    const float* l0_bq = (const float*)d_in[5];
    const float* l0_Wk = (const float*)d_in[6];
    const float* l0_bk = (const float*)d_in[7];
    const float* l0_Wv = (const float*)d_in[8];
    const float* l0_bv = (const float*)d_in[9];
    const float* l0_We = (const float*)d_in[10];
    const float* l0_Ws = (const float*)d_in[11];
    const float* l0_bs = (const float*)d_in[12];
    const float* l1_Wq = (const float*)d_in[13];
    const float* l1_bq = (const float*)d_in[14];
    const float* l1_Wk = (const float*)d_in[15];
    const float* l1_bk = (const float*)d_in[16];
    const float* l1_Wv = (const float*)d_in[17];
    const float* l1_bv = (const float*)d_in[18];
    const float* l1_We = (const float*)d_in[19];
    const float* l1_Ws = (const float*)d_in[20];
    const float* l1_bs = (const float*)d_in[21];
    const float* cW1   = (const float*)d_in[22];
    const float* cb1   = (const float*)d_in[23];
    const float* cW2   = (const float*)d_in[24];
    const float* cb2   = (const float*)d_in[25];
    float* out = (float*)d_out;

    int N = in_sizes[3];       // batch length = #nodes
    int E = in_sizes[2];       // edge_attr length = #edges
    const int* src = ei;
    const int* dst = ei + E;

    // CSR build (reused by both layers)
    zero_kernel<<<(N + 255) / 256, 256>>>(N);
    hist_kernel<<<(E + 255) / 256, 256>>>(dst, batch, N, E);
    scan_kernel<<<1, 1024>>>(N);
    scatter_kernel<<<(E + 255) / 256, 256>>>(src, dst, eattr, E);

    // layer 0: algebraically collapsed (in_ch = 2)
    prep0_kernel<<<1, 32>>>(l0_Wq, l0_bq, l0_Wk, l0_bk, l0_We);
    attn0_kernel<<<(N + 127) / 128, 128>>>(x, N);
    expand0_kernel<<<(N * 32 + 255) / 256, 256>>>(x, l0_Wv, l0_bv, l0_We, l0_Ws, l0_bs, N);

    // layer 1 projections: fused 3-pass fp16-split tensor-core GEMM
    dim3 ggrid((N + 127) / 128, 4);
    gemm3_kernel<<<ggrid, 256>>>(l1_Wq, l1_Wk, l1_Wv, l1_Ws,
                                 l1_bq, l1_bk, l1_bv, l1_bs);

    attn_kernel<<<(N * 32 + 255) / 256, 256>>>(l1_We, N);

    // pool (two-stage) + head
    dim3 pgrid(GMAX, 8);
    pool_kernel<<<pgrid, HD>>>();
    classifier_kernel<<<GMAX, HD>>>(cW1, cb1, cW2, cb2, out);
}